// round 2
// baseline (speedup 1.0000x reference)
#include <cuda_runtime.h>
#include <math.h>

// ---- problem dims ----
#define TT   2048      // tokens = B*S
#define HD   1024      // hidden
#define ID   2816      // expert intermediate
#define NE   8         // experts
#define ISD  1408      // shared intermediate

// ---- scratch (device globals; no allocation allowed) ----
__device__ int   g_count[NE];
__device__ int   g_tok[NE][TT];
__device__ int   g_slot[NE][TT];
__device__ float g_p[TT][2];
__device__ float g_act[(size_t)TT * 2 * ID];     // SwiGLU activations per (token,slot)
__device__ float g_dslot[(size_t)TT * 2 * HD];   // down-proj output per (token,slot)
__device__ float g_shact[(size_t)TT * ISD];      // shared-expert activations

__global__ void zero_counts_kernel() {
    if (threadIdx.x < NE) g_count[threadIdx.x] = 0;
}

// Router: logits -> top-2 -> softmax(2) -> push to per-expert lists
__global__ void router_kernel(const float* __restrict__ x,
                              const float* __restrict__ gw) {
    int t = blockIdx.x * blockDim.x + threadIdx.x;
    if (t >= TT) return;
    float lg[NE];
#pragma unroll
    for (int e = 0; e < NE; e++) lg[e] = 0.f;
    const float* xr = x + (size_t)t * HD;
    for (int h = 0; h < HD; h++) {
        float xv = xr[h];
#pragma unroll
        for (int e = 0; e < NE; e++) lg[e] = fmaf(xv, gw[h * NE + e], lg[e]);
    }
    int i0 = 0; float v0 = lg[0];
#pragma unroll
    for (int e = 1; e < NE; e++) if (lg[e] > v0) { v0 = lg[e]; i0 = e; }
    int i1 = -1; float v1 = -INFINITY;
#pragma unroll
    for (int e = 0; e < NE; e++) if (e != i0 && lg[e] > v1) { v1 = lg[e]; i1 = e; }
    float e1 = expf(v1 - v0);
    float inv = 1.f / (1.f + e1);
    g_p[t][0] = inv;
    g_p[t][1] = e1 * inv;
    int pos0 = atomicAdd(&g_count[i0], 1);
    g_tok[i0][pos0] = t; g_slot[i0][pos0] = 0;
    int pos1 = atomicAdd(&g_count[i1], 1);
    g_tok[i1][pos1] = t; g_slot[i1][pos1] = 1;
}

// ---- Grouped gate+up GEMM: act = silu(X@Wg[e]) * (X@Wu[e]) over gathered rows ----
// BM=BN=64, BK=16, 256 threads, 4x4 per-thread (x2 for g/u)
__global__ void expert_gateup_kernel(const float* __restrict__ x,
                                     const float* __restrict__ Wg,
                                     const float* __restrict__ Wu) {
    const int e   = blockIdx.z;
    const int cnt = g_count[e];
    const int m0  = blockIdx.x * 64;
    if (m0 >= cnt) return;
    const int n0  = blockIdx.y * 64;

    __shared__ float As[16][64];
    __shared__ float Bg[16][64];
    __shared__ float Bu[16][64];

    const int tid  = threadIdx.x;
    const int tx   = tid & 15, ty = tid >> 4;
    const int rowA = tid >> 2;
    const int kA   = (tid & 3) * 4;
    const int kB   = tid >> 4;
    const int nB   = (tid & 15) * 4;

    bool avalid = (m0 + rowA) < cnt;
    int tok = avalid ? g_tok[e][m0 + rowA] : 0;
    const float* xrow = x + (size_t)tok * HD;
    const float* pg = Wg + (size_t)e * HD * ID + n0;
    const float* pu = Wu + (size_t)e * HD * ID + n0;

    float ag[4][4] = {}; float au[4][4] = {};
    for (int k0 = 0; k0 < HD; k0 += 16) {
        float4 av = make_float4(0.f, 0.f, 0.f, 0.f);
        if (avalid) av = *(const float4*)(xrow + k0 + kA);
        As[kA + 0][rowA] = av.x; As[kA + 1][rowA] = av.y;
        As[kA + 2][rowA] = av.z; As[kA + 3][rowA] = av.w;
        *(float4*)&Bg[kB][nB] = *(const float4*)(pg + (size_t)(k0 + kB) * ID + nB);
        *(float4*)&Bu[kB][nB] = *(const float4*)(pu + (size_t)(k0 + kB) * ID + nB);
        __syncthreads();
#pragma unroll
        for (int kk = 0; kk < 16; kk++) {
            float4 a4  = *(const float4*)&As[kk][ty * 4];
            float4 bg4 = *(const float4*)&Bg[kk][tx * 4];
            float4 bu4 = *(const float4*)&Bu[kk][tx * 4];
            float aa[4]  = {a4.x, a4.y, a4.z, a4.w};
            float bgv[4] = {bg4.x, bg4.y, bg4.z, bg4.w};
            float buv[4] = {bu4.x, bu4.y, bu4.z, bu4.w};
#pragma unroll
            for (int i = 0; i < 4; i++)
#pragma unroll
                for (int j = 0; j < 4; j++) {
                    ag[i][j] = fmaf(aa[i], bgv[j], ag[i][j]);
                    au[i][j] = fmaf(aa[i], buv[j], au[i][j]);
                }
        }
        __syncthreads();
    }
#pragma unroll
    for (int i = 0; i < 4; i++) {
        int r = m0 + ty * 4 + i;
        if (r < cnt) {
            int flat = g_tok[e][r] * 2 + g_slot[e][r];
            float4 o;
            float* po = (float*)&o;
#pragma unroll
            for (int j = 0; j < 4; j++) {
                float g = ag[i][j], u = au[i][j];
                po[j] = u * g / (1.f + expf(-g));
            }
            *(float4*)(g_act + (size_t)flat * ID + n0 + tx * 4) = o;
        }
    }
}

// ---- Grouped down GEMM: dslot = act @ Wd[e] over gathered rows ----
__global__ void expert_down_kernel(const float* __restrict__ Wd) {
    const int e   = blockIdx.z;
    const int cnt = g_count[e];
    const int m0  = blockIdx.x * 64;
    if (m0 >= cnt) return;
    const int n0  = blockIdx.y * 64;

    __shared__ float As[16][64];
    __shared__ float Bs[16][64];

    const int tid  = threadIdx.x;
    const int tx   = tid & 15, ty = tid >> 4;
    const int rowA = tid >> 2;
    const int kA   = (tid & 3) * 4;
    const int kB   = tid >> 4;
    const int nB   = (tid & 15) * 4;

    bool avalid = (m0 + rowA) < cnt;
    const float* arow = g_act;  // base
    if (avalid) {
        int flat = g_tok[e][m0 + rowA] * 2 + g_slot[e][m0 + rowA];
        arow = g_act + (size_t)flat * ID;
    }
    const float* pb = Wd + (size_t)e * ID * HD + n0;

    float acc[4][4] = {};
    for (int k0 = 0; k0 < ID; k0 += 16) {
        float4 av = make_float4(0.f, 0.f, 0.f, 0.f);
        if (avalid) av = *(const float4*)(arow + k0 + kA);
        As[kA + 0][rowA] = av.x; As[kA + 1][rowA] = av.y;
        As[kA + 2][rowA] = av.z; As[kA + 3][rowA] = av.w;
        *(float4*)&Bs[kB][nB] = *(const float4*)(pb + (size_t)(k0 + kB) * HD + nB);
        __syncthreads();
#pragma unroll
        for (int kk = 0; kk < 16; kk++) {
            float4 a4 = *(const float4*)&As[kk][ty * 4];
            float4 b4 = *(const float4*)&Bs[kk][tx * 4];
            float aa[4] = {a4.x, a4.y, a4.z, a4.w};
            float bb[4] = {b4.x, b4.y, b4.z, b4.w};
#pragma unroll
            for (int i = 0; i < 4; i++)
#pragma unroll
                for (int j = 0; j < 4; j++)
                    acc[i][j] = fmaf(aa[i], bb[j], acc[i][j]);
        }
        __syncthreads();
    }
#pragma unroll
    for (int i = 0; i < 4; i++) {
        int r = m0 + ty * 4 + i;
        if (r < cnt) {
            int flat = g_tok[e][r] * 2 + g_slot[e][r];
            float4 o = make_float4(acc[i][0], acc[i][1], acc[i][2], acc[i][3]);
            *(float4*)(g_dslot + (size_t)flat * HD + n0 + tx * 4) = o;
        }
    }
}

// ---- Shared expert gate+up: g_shact = silu(X@Sg) * (X@Su) ----
__global__ void shared_gateup_kernel(const float* __restrict__ x,
                                     const float* __restrict__ Sg,
                                     const float* __restrict__ Su) {
    const int m0 = blockIdx.x * 64;
    const int n0 = blockIdx.y * 64;

    __shared__ float As[16][64];
    __shared__ float Bg[16][64];
    __shared__ float Bu[16][64];

    const int tid  = threadIdx.x;
    const int tx   = tid & 15, ty = tid >> 4;
    const int rowA = tid >> 2;
    const int kA   = (tid & 3) * 4;
    const int kB   = tid >> 4;
    const int nB   = (tid & 15) * 4;

    const float* xrow = x + (size_t)(m0 + rowA) * HD;
    const float* pg = Sg + n0;
    const float* pu = Su + n0;

    float ag[4][4] = {}; float au[4][4] = {};
    for (int k0 = 0; k0 < HD; k0 += 16) {
        float4 av = *(const float4*)(xrow + k0 + kA);
        As[kA + 0][rowA] = av.x; As[kA + 1][rowA] = av.y;
        As[kA + 2][rowA] = av.z; As[kA + 3][rowA] = av.w;
        *(float4*)&Bg[kB][nB] = *(const float4*)(pg + (size_t)(k0 + kB) * ISD + nB);
        *(float4*)&Bu[kB][nB] = *(const float4*)(pu + (size_t)(k0 + kB) * ISD + nB);
        __syncthreads();
#pragma unroll
        for (int kk = 0; kk < 16; kk++) {
            float4 a4  = *(const float4*)&As[kk][ty * 4];
            float4 bg4 = *(const float4*)&Bg[kk][tx * 4];
            float4 bu4 = *(const float4*)&Bu[kk][tx * 4];
            float aa[4]  = {a4.x, a4.y, a4.z, a4.w};
            float bgv[4] = {bg4.x, bg4.y, bg4.z, bg4.w};
            float buv[4] = {bu4.x, bu4.y, bu4.z, bu4.w};
#pragma unroll
            for (int i = 0; i < 4; i++)
#pragma unroll
                for (int j = 0; j < 4; j++) {
                    ag[i][j] = fmaf(aa[i], bgv[j], ag[i][j]);
                    au[i][j] = fmaf(aa[i], buv[j], au[i][j]);
                }
        }
        __syncthreads();
    }
#pragma unroll
    for (int i = 0; i < 4; i++) {
        int t = m0 + ty * 4 + i;
        float4 o;
        float* po = (float*)&o;
#pragma unroll
        for (int j = 0; j < 4; j++) {
            float g = ag[i][j], u = au[i][j];
            po[j] = u * g / (1.f + expf(-g));
        }
        *(float4*)(g_shact + (size_t)t * ISD + n0 + tx * 4) = o;
    }
}

// ---- Shared down GEMM fused with final combine:
//      out = g_shact @ Sd + p0*dslot[t,0] + p1*dslot[t,1] ----
__global__ void shared_down_combine_kernel(const float* __restrict__ Sd,
                                           float* __restrict__ out) {
    const int m0 = blockIdx.x * 64;
    const int n0 = blockIdx.y * 64;

    __shared__ float As[16][64];
    __shared__ float Bs[16][64];

    const int tid  = threadIdx.x;
    const int tx   = tid & 15, ty = tid >> 4;
    const int rowA = tid >> 2;
    const int kA   = (tid & 3) * 4;
    const int kB   = tid >> 4;
    const int nB   = (tid & 15) * 4;

    const float* arow = g_shact + (size_t)(m0 + rowA) * ISD;
    const float* pb = Sd + n0;

    float acc[4][4] = {};
    for (int k0 = 0; k0 < ISD; k0 += 16) {
        float4 av = *(const float4*)(arow + k0 + kA);
        As[kA + 0][rowA] = av.x; As[kA + 1][rowA] = av.y;
        As[kA + 2][rowA] = av.z; As[kA + 3][rowA] = av.w;
        *(float4*)&Bs[kB][nB] = *(const float4*)(pb + (size_t)(k0 + kB) * HD + nB);
        __syncthreads();
#pragma unroll
        for (int kk = 0; kk < 16; kk++) {
            float4 a4 = *(const float4*)&As[kk][ty * 4];
            float4 b4 = *(const float4*)&Bs[kk][tx * 4];
            float aa[4] = {a4.x, a4.y, a4.z, a4.w};
            float bb[4] = {b4.x, b4.y, b4.z, b4.w};
#pragma unroll
            for (int i = 0; i < 4; i++)
#pragma unroll
                for (int j = 0; j < 4; j++)
                    acc[i][j] = fmaf(aa[i], bb[j], acc[i][j]);
        }
        __syncthreads();
    }
#pragma unroll
    for (int i = 0; i < 4; i++) {
        int t = m0 + ty * 4 + i;
        float p0 = g_p[t][0];
        float p1 = g_p[t][1];
        const float* d0 = g_dslot + (size_t)(t * 2) * HD + n0 + tx * 4;
        const float* d1 = d0 + HD;
        float4 v0 = *(const float4*)d0;
        float4 v1 = *(const float4*)d1;
        float4 o;
        o.x = acc[i][0] + p0 * v0.x + p1 * v1.x;
        o.y = acc[i][1] + p0 * v0.y + p1 * v1.y;
        o.z = acc[i][2] + p0 * v0.z + p1 * v1.z;
        o.w = acc[i][3] + p0 * v0.w + p1 * v1.w;
        *(float4*)(out + (size_t)t * HD + n0 + tx * 4) = o;
    }
}

extern "C" void kernel_launch(void* const* d_in, const int* in_sizes, int n_in,
                              void* d_out, int out_size) {
    const float* x      = (const float*)d_in[0];  // [B,S,H]
    const float* gate_w = (const float*)d_in[1];  // [H,E]
    const float* Wg     = (const float*)d_in[2];  // [E,H,I]
    const float* Wu     = (const float*)d_in[3];  // [E,H,I]
    const float* Wd     = (const float*)d_in[4];  // [E,I,H]
    const float* Sg     = (const float*)d_in[5];  // [H,IS]
    const float* Su     = (const float*)d_in[6];  // [H,IS]
    const float* Sd     = (const float*)d_in[7];  // [IS,H]
    float* out = (float*)d_out;

    zero_counts_kernel<<<1, 32>>>();
    router_kernel<<<TT / 256, 256>>>(x, gate_w);

    dim3 gGU(TT / 64, ID / 64, NE);     // 32 x 44 x 8 (early-exit on count)
    expert_gateup_kernel<<<gGU, 256>>>(x, Wg, Wu);

    dim3 gD(TT / 64, HD / 64, NE);      // 32 x 16 x 8
    expert_down_kernel<<<gD, 256>>>(Wd);

    dim3 gSGU(TT / 64, ISD / 64);       // 32 x 22
    shared_gateup_kernel<<<gSGU, 256>>>(x, Sg, Su);

    dim3 gSD(TT / 64, HD / 64);         // 32 x 16
    shared_down_combine_kernel<<<gSD, 256>>>(Sd, out);
}

// round 4
// speedup vs baseline: 2.3885x; 2.3885x over previous
#include <cuda_runtime.h>
#include <cuda_bf16.h>
#include <math.h>

#define TT   2048
#define HD   1024
#define ID   2816
#define NE   8
#define ISD  1408

// ---- routing scratch ----
__device__ int   g_count[NE];
__device__ int   g_tok[NE][TT];
__device__ int   g_slot[NE][TT];
__device__ float g_p[TT][2];
__device__ float g_dslot[(size_t)TT * 2 * HD];

// ---- bf16 hi/lo split copies (persistent device globals) ----
__device__ __nv_bfloat16 g_Wghi[(size_t)NE * HD * ID];
__device__ __nv_bfloat16 g_Wglo[(size_t)NE * HD * ID];
__device__ __nv_bfloat16 g_Wuhi[(size_t)NE * HD * ID];
__device__ __nv_bfloat16 g_Wulo[(size_t)NE * HD * ID];
__device__ __nv_bfloat16 g_Wdhi[(size_t)NE * ID * HD];
__device__ __nv_bfloat16 g_Wdlo[(size_t)NE * ID * HD];
__device__ __nv_bfloat16 g_Sghi[(size_t)HD * ISD];
__device__ __nv_bfloat16 g_Sglo[(size_t)HD * ISD];
__device__ __nv_bfloat16 g_Suhi[(size_t)HD * ISD];
__device__ __nv_bfloat16 g_Sulo[(size_t)HD * ISD];
__device__ __nv_bfloat16 g_Sdhi[(size_t)ISD * HD];
__device__ __nv_bfloat16 g_Sdlo[(size_t)ISD * HD];
__device__ __nv_bfloat16 g_xhi[(size_t)TT * HD];
__device__ __nv_bfloat16 g_xlo[(size_t)TT * HD];
__device__ __nv_bfloat16 g_acthi[(size_t)TT * 2 * ID];
__device__ __nv_bfloat16 g_actlo[(size_t)TT * 2 * ID];
__device__ __nv_bfloat16 g_shacthi[(size_t)TT * ISD];
__device__ __nv_bfloat16 g_shactlo[(size_t)TT * ISD];

// =================== helpers ===================
__device__ __forceinline__ unsigned s2u(const void* p) {
    return (unsigned)__cvta_generic_to_shared(p);
}
__device__ __forceinline__ unsigned swz(unsigned o) { return o ^ ((o >> 3) & 0x70); }

__device__ __forceinline__ void split2(float f0, float f1, unsigned& hi, unsigned& lo) {
    __nv_bfloat16 h0 = __float2bfloat16_rn(f0);
    __nv_bfloat16 h1 = __float2bfloat16_rn(f1);
    __nv_bfloat16 l0 = __float2bfloat16_rn(f0 - __bfloat162float(h0));
    __nv_bfloat16 l1 = __float2bfloat16_rn(f1 - __bfloat162float(h1));
    hi = (unsigned)__bfloat16_as_ushort(h0) | ((unsigned)__bfloat16_as_ushort(h1) << 16);
    lo = (unsigned)__bfloat16_as_ushort(l0) | ((unsigned)__bfloat16_as_ushort(l1) << 16);
}

__device__ __forceinline__ void sts128(unsigned a, uint4 v) {
    asm volatile("st.shared.v4.b32 [%0], {%1,%2,%3,%4};"
                 :: "r"(a), "r"(v.x), "r"(v.y), "r"(v.z), "r"(v.w));
}
__device__ __forceinline__ void ldsm4(unsigned a, unsigned* r) {
    asm volatile("ldmatrix.sync.aligned.m8n8.x4.shared.b16 {%0,%1,%2,%3}, [%4];"
                 : "=r"(r[0]), "=r"(r[1]), "=r"(r[2]), "=r"(r[3]) : "r"(a));
}
__device__ __forceinline__ void ldsm4t(unsigned a, unsigned* r) {
    asm volatile("ldmatrix.sync.aligned.m8n8.x4.trans.shared.b16 {%0,%1,%2,%3}, [%4];"
                 : "=r"(r[0]), "=r"(r[1]), "=r"(r[2]), "=r"(r[3]) : "r"(a));
}
__device__ __forceinline__ void mma16816(float* c, const unsigned* a, const unsigned* b) {
    asm volatile("mma.sync.aligned.m16n8k16.row.col.f32.bf16.bf16.f32 "
                 "{%0,%1,%2,%3}, {%4,%5,%6,%7}, {%8,%9}, {%0,%1,%2,%3};"
                 : "+f"(c[0]), "+f"(c[1]), "+f"(c[2]), "+f"(c[3])
                 : "r"(a[0]), "r"(a[1]), "r"(a[2]), "r"(a[3]), "r"(b[0]), "r"(b[1]));
}
__device__ __forceinline__ float silu_mul(float g, float u) {
    return u * g / (1.f + __expf(-g));
}

// =================== splitter ===================
__global__ void split_kernel(const float4* __restrict__ src, int sel, int n4) {
    uint2* hi; uint2* lo;
    switch (sel) {
        case 0: hi = (uint2*)g_Wghi; lo = (uint2*)g_Wglo; break;
        case 1: hi = (uint2*)g_Wuhi; lo = (uint2*)g_Wulo; break;
        case 2: hi = (uint2*)g_Wdhi; lo = (uint2*)g_Wdlo; break;
        case 3: hi = (uint2*)g_Sghi; lo = (uint2*)g_Sglo; break;
        case 4: hi = (uint2*)g_Suhi; lo = (uint2*)g_Sulo; break;
        case 5: hi = (uint2*)g_Sdhi; lo = (uint2*)g_Sdlo; break;
        default: hi = (uint2*)g_xhi; lo = (uint2*)g_xlo; break;
    }
    int stride = gridDim.x * blockDim.x;
    for (int i = blockIdx.x * blockDim.x + threadIdx.x; i < n4; i += stride) {
        float4 v = src[i];
        unsigned h0, l0, h1, l1;
        split2(v.x, v.y, h0, l0);
        split2(v.z, v.w, h1, l1);
        hi[i] = make_uint2(h0, h1);
        lo[i] = make_uint2(l0, l1);
    }
}

// =================== router ===================
__global__ void zero_counts_kernel() { if (threadIdx.x < NE) g_count[threadIdx.x] = 0; }

__global__ void router_kernel(const float* __restrict__ x, const float* __restrict__ gw) {
    int t = blockIdx.x * blockDim.x + threadIdx.x;
    if (t >= TT) return;
    float lg[NE];
#pragma unroll
    for (int e = 0; e < NE; e++) lg[e] = 0.f;
    const float* xr = x + (size_t)t * HD;
    for (int h = 0; h < HD; h++) {
        float xv = xr[h];
#pragma unroll
        for (int e = 0; e < NE; e++) lg[e] = fmaf(xv, gw[h * NE + e], lg[e]);
    }
    int i0 = 0; float v0 = lg[0];
#pragma unroll
    for (int e = 1; e < NE; e++) if (lg[e] > v0) { v0 = lg[e]; i0 = e; }
    int i1 = -1; float v1 = -INFINITY;
#pragma unroll
    for (int e = 0; e < NE; e++) if (e != i0 && lg[e] > v1) { v1 = lg[e]; i1 = e; }
    float e1 = expf(v1 - v0);
    float inv = 1.f / (1.f + e1);
    g_p[t][0] = inv;
    g_p[t][1] = e1 * inv;
    int p0 = atomicAdd(&g_count[i0], 1);
    g_tok[i0][p0] = t; g_slot[i0][p0] = 0;
    int p1 = atomicAdd(&g_count[i1], 1);
    g_tok[i1][p1] = t; g_slot[i1][p1] = 1;
}

// =================== gate+up HMMA GEMM (BM=128, BN=64, BK=64) ===================
// smem buffer: A hi 16K | A lo 16K | Bg hi 8K | Bg lo 8K | Bu hi 8K | Bu lo 8K = 64K
#define GU_AH  0u
#define GU_AL  16384u
#define GU_BGH 32768u
#define GU_BGL 40960u
#define GU_BUH 49152u
#define GU_BUL 57344u
#define BUFSZ  65536u

template<bool SHARED>
__global__ void __launch_bounds__(256, 1) gateup_hmma() {
    constexpr int K_TOT = HD;
    constexpr int N_TOT = SHARED ? ISD : ID;
    constexpr int NK = K_TOT / 64;
    const int tid = threadIdx.x, l = tid & 31, wid = tid >> 5;
    const int m0 = blockIdx.x * 128, n0 = blockIdx.y * 64;
    const int e = SHARED ? 0 : blockIdx.z;
    int cnt = TT;
    if (!SHARED) { cnt = g_count[e]; if (m0 >= cnt) return; }

    const __nv_bfloat16* Bgh = (SHARED ? g_Sghi : g_Wghi + (size_t)e * K_TOT * N_TOT) + n0;
    const __nv_bfloat16* Bgl = (SHARED ? g_Sglo : g_Wglo + (size_t)e * K_TOT * N_TOT) + n0;
    const __nv_bfloat16* Buh = (SHARED ? g_Suhi : g_Wuhi + (size_t)e * K_TOT * N_TOT) + n0;
    const __nv_bfloat16* Bul = (SHARED ? g_Sulo : g_Wulo + (size_t)e * K_TOT * N_TOT) + n0;
    __nv_bfloat16* Ohi = SHARED ? g_shacthi : g_acthi;
    __nv_bfloat16* Olo = SHARED ? g_shactlo : g_actlo;

    size_t aoff[4];
#pragma unroll
    for (int p = 0; p < 4; p++) {
        int idx = m0 + p * 32 + (tid >> 3);
        if (!SHARED) {
            int ci = idx < cnt ? idx : cnt - 1;
            aoff[p] = (size_t)g_tok[e][ci] * HD;
        } else {
            aoff[p] = (size_t)idx * HD;
        }
    }

    extern __shared__ char dyn[];
    unsigned sb = (s2u(dyn) + 127) & ~127u;

    auto LDG = [&](int kt, uint4* ra, uint4* rb) {
        int k0 = kt * 64;
#pragma unroll
        for (int p = 0; p < 4; p++) {
            size_t o = aoff[p] + k0 + (tid & 7) * 8;
            ra[2 * p + 0] = *(const uint4*)(g_xhi + o);
            ra[2 * p + 1] = *(const uint4*)(g_xlo + o);
        }
#pragma unroll
        for (int p = 0; p < 2; p++) {
            int s = p * 256 + tid;
            size_t o = (size_t)(k0 + (s >> 3)) * N_TOT + (s & 7) * 8;
            rb[p * 4 + 0] = *(const uint4*)(Bgh + o);
            rb[p * 4 + 1] = *(const uint4*)(Bgl + o);
            rb[p * 4 + 2] = *(const uint4*)(Buh + o);
            rb[p * 4 + 3] = *(const uint4*)(Bul + o);
        }
    };
    auto STS = [&](int st, uint4* ra, uint4* rb) {
        unsigned bb = sb + st * BUFSZ;
#pragma unroll
        for (int p = 0; p < 4; p++) {
            unsigned d = swz((p * 32 + (tid >> 3)) * 128 + (tid & 7) * 16);
            sts128(bb + GU_AH + d, ra[2 * p + 0]);
            sts128(bb + GU_AL + d, ra[2 * p + 1]);
        }
#pragma unroll
        for (int p = 0; p < 2; p++) {
            int s = p * 256 + tid;
            unsigned d = swz((s >> 3) * 128 + (s & 7) * 16);
            sts128(bb + GU_BGH + d, rb[p * 4 + 0]);
            sts128(bb + GU_BGL + d, rb[p * 4 + 1]);
            sts128(bb + GU_BUH + d, rb[p * 4 + 2]);
            sts128(bb + GU_BUL + d, rb[p * 4 + 3]);
        }
    };

    float cg[4][2][4] = {}, cu[4][2][4] = {};
    const int wm = (wid & 1) * 64, wn = (wid >> 1) * 16;
    const unsigned aRowB = (unsigned)(wm + (l & 15)) * 128;
    const unsigned sx = l & 7;
    const unsigned aCx = (l >> 4) & 1;
    const unsigned bKr = (l & 7) + ((l >> 3) & 1) * 8;
    const unsigned bG2 = (l >> 4) & 1;
    const unsigned bCk = ((((unsigned)wn >> 3) + bG2) ^ sx) << 4;

    auto COMPUTE = [&](int st) {
        unsigned bb = sb + st * BUFSZ;
#pragma unroll
        for (int ks = 0; ks < 4; ks++) {
            unsigned cka = (((unsigned)(ks * 2) + aCx) ^ sx) << 4;
            unsigned ah[4][4], al[4][4];
#pragma unroll
            for (int mf = 0; mf < 4; mf++) {
                unsigned ad = bb + aRowB + mf * 2048 + cka;
                ldsm4(ad + GU_AH, ah[mf]);
                ldsm4(ad + GU_AL, al[mf]);
            }
            unsigned brow = (unsigned)(ks * 16 + bKr) * 128 + bCk;
            unsigned bgh[4], bgl[4], buh[4], bul[4];
            ldsm4t(bb + GU_BGH + brow, bgh);
            ldsm4t(bb + GU_BGL + brow, bgl);
            ldsm4t(bb + GU_BUH + brow, buh);
            ldsm4t(bb + GU_BUL + brow, bul);
#pragma unroll
            for (int mf = 0; mf < 4; mf++)
#pragma unroll
                for (int nf = 0; nf < 2; nf++) {
                    mma16816(cg[mf][nf], ah[mf], bgh + nf * 2);
                    mma16816(cg[mf][nf], al[mf], bgh + nf * 2);
                    mma16816(cg[mf][nf], ah[mf], bgl + nf * 2);
                    mma16816(cu[mf][nf], ah[mf], buh + nf * 2);
                    mma16816(cu[mf][nf], al[mf], buh + nf * 2);
                    mma16816(cu[mf][nf], ah[mf], bul + nf * 2);
                }
        }
    };

    uint4 ra[8], rb[8];
    LDG(0, ra, rb);
    STS(0, ra, rb);
#pragma unroll 1
    for (int kt = 0; kt < NK; kt++) {
        __syncthreads();
        if (kt + 1 < NK) LDG(kt + 1, ra, rb);
        COMPUTE(kt & 1);
        if (kt + 1 < NK) STS((kt + 1) & 1, ra, rb);
    }

    // epilogue: silu(g)*u -> bf16 hi/lo
    const int rr = m0 + wm + (l >> 2);
    const int cc0 = n0 + wn + (l & 3) * 2;
#pragma unroll
    for (int mf = 0; mf < 4; mf++) {
#pragma unroll
        for (int h = 0; h < 2; h++) {
            int r = rr + mf * 16 + h * 8;
            size_t obase;
            if (!SHARED) {
                if (r >= cnt) continue;
                int flat = g_tok[e][r] * 2 + g_slot[e][r];
                obase = (size_t)flat * N_TOT;
            } else {
                obase = (size_t)r * N_TOT;
            }
#pragma unroll
            for (int nf = 0; nf < 2; nf++) {
                float a0 = silu_mul(cg[mf][nf][h * 2 + 0], cu[mf][nf][h * 2 + 0]);
                float a1 = silu_mul(cg[mf][nf][h * 2 + 1], cu[mf][nf][h * 2 + 1]);
                unsigned hi, lo;
                split2(a0, a1, hi, lo);
                size_t off = obase + cc0 + nf * 8;
                *(unsigned*)(Ohi + off) = hi;
                *(unsigned*)(Olo + off) = lo;
            }
        }
    }
}

// =================== down HMMA GEMM (BM=128, BN=128, BK=64) ===================
// smem buffer: A hi 16K | A lo 16K | B hi 16K (2 halves) | B lo 16K = 64K
#define DN_AH 0u
#define DN_AL 16384u
#define DN_BH 32768u
#define DN_BL 49152u

template<bool SHARED>
__global__ void __launch_bounds__(256, 1) down_hmma(float* __restrict__ Out) {
    constexpr int K_TOT = SHARED ? ISD : ID;
    constexpr int NK = K_TOT / 64;
    const int tid = threadIdx.x, l = tid & 31, wid = tid >> 5;
    const int m0 = blockIdx.x * 128, n0 = blockIdx.y * 128;
    const int e = SHARED ? 0 : blockIdx.z;
    int cnt = TT;
    if (!SHARED) { cnt = g_count[e]; if (m0 >= cnt) return; }

    const __nv_bfloat16* Bh = (SHARED ? g_Sdhi : g_Wdhi + (size_t)e * K_TOT * HD) + n0;
    const __nv_bfloat16* Bl = (SHARED ? g_Sdlo : g_Wdlo + (size_t)e * K_TOT * HD) + n0;
    const __nv_bfloat16* Ahi = SHARED ? g_shacthi : g_acthi;
    const __nv_bfloat16* Alo = SHARED ? g_shactlo : g_actlo;

    size_t aoff[4];
#pragma unroll
    for (int p = 0; p < 4; p++) {
        int idx = m0 + p * 32 + (tid >> 3);
        if (!SHARED) {
            int ci = idx < cnt ? idx : cnt - 1;
            aoff[p] = (size_t)(g_tok[e][ci] * 2 + g_slot[e][ci]) * K_TOT;
        } else {
            aoff[p] = (size_t)idx * K_TOT;
        }
    }

    extern __shared__ char dyn[];
    unsigned sb = (s2u(dyn) + 127) & ~127u;

    auto LDG = [&](int kt, uint4* ra, uint4* rb) {
        int k0 = kt * 64;
#pragma unroll
        for (int p = 0; p < 4; p++) {
            size_t o = aoff[p] + k0 + (tid & 7) * 8;
            ra[2 * p + 0] = *(const uint4*)(Ahi + o);
            ra[2 * p + 1] = *(const uint4*)(Alo + o);
        }
#pragma unroll
        for (int p = 0; p < 4; p++) {
            int s = p * 256 + tid;
            size_t o = (size_t)(k0 + (s >> 4)) * HD + (s & 15) * 8;
            rb[p * 2 + 0] = *(const uint4*)(Bh + o);
            rb[p * 2 + 1] = *(const uint4*)(Bl + o);
        }
    };
    auto STS = [&](int st, uint4* ra, uint4* rb) {
        unsigned bb = sb + st * BUFSZ;
#pragma unroll
        for (int p = 0; p < 4; p++) {
            unsigned d = swz((p * 32 + (tid >> 3)) * 128 + (tid & 7) * 16);
            sts128(bb + DN_AH + d, ra[2 * p + 0]);
            sts128(bb + DN_AL + d, ra[2 * p + 1]);
        }
#pragma unroll
        for (int p = 0; p < 4; p++) {
            int s = p * 256 + tid;
            int kk = s >> 4, c16 = s & 15;
            unsigned d = (unsigned)(c16 >> 3) * 8192 + swz(kk * 128 + (c16 & 7) * 16);
            sts128(bb + DN_BH + d, rb[p * 2 + 0]);
            sts128(bb + DN_BL + d, rb[p * 2 + 1]);
        }
    };

    float cc[4][4][4] = {};
    const int wm = (wid & 1) * 64, wn = (wid >> 1) * 32;
    const unsigned aRowB = (unsigned)(wm + (l & 15)) * 128;
    const unsigned sx = l & 7;
    const unsigned aCx = (l >> 4) & 1;
    const unsigned bKr = (l & 7) + ((l >> 3) & 1) * 8;
    const unsigned bG2 = (l >> 4) & 1;
    const unsigned hoff = (unsigned)(wn >> 6) * 8192;
    const unsigned nq = ((unsigned)wn & 63) >> 3;
    const unsigned ck0 = ((nq + 0 + bG2) ^ sx) << 4;
    const unsigned ck1 = ((nq + 2 + bG2) ^ sx) << 4;

    auto COMPUTE = [&](int st) {
        unsigned bb = sb + st * BUFSZ;
#pragma unroll
        for (int ks = 0; ks < 4; ks++) {
            unsigned cka = (((unsigned)(ks * 2) + aCx) ^ sx) << 4;
            unsigned ah[4][4], al[4][4];
#pragma unroll
            for (int mf = 0; mf < 4; mf++) {
                unsigned ad = bb + aRowB + mf * 2048 + cka;
                ldsm4(ad + DN_AH, ah[mf]);
                ldsm4(ad + DN_AL, al[mf]);
            }
            unsigned brow = (unsigned)(ks * 16 + bKr) * 128;
            unsigned bh[8], bl[8];
            ldsm4t(bb + DN_BH + hoff + brow + ck0, bh);
            ldsm4t(bb + DN_BH + hoff + brow + ck1, bh + 4);
            ldsm4t(bb + DN_BL + hoff + brow + ck0, bl);
            ldsm4t(bb + DN_BL + hoff + brow + ck1, bl + 4);
#pragma unroll
            for (int mf = 0; mf < 4; mf++)
#pragma unroll
                for (int nf = 0; nf < 4; nf++) {
                    mma16816(cc[mf][nf], ah[mf], bh + nf * 2);
                    mma16816(cc[mf][nf], al[mf], bh + nf * 2);
                    mma16816(cc[mf][nf], ah[mf], bl + nf * 2);
                }
        }
    };

    uint4 ra[8], rb[8];
    LDG(0, ra, rb);
    STS(0, ra, rb);
#pragma unroll 1
    for (int kt = 0; kt < NK; kt++) {
        __syncthreads();
        if (kt + 1 < NK) LDG(kt + 1, ra, rb);
        COMPUTE(kt & 1);
        if (kt + 1 < NK) STS((kt + 1) & 1, ra, rb);
    }

    const int rr = m0 + wm + (l >> 2);
    const int cc0 = n0 + wn + (l & 3) * 2;
#pragma unroll
    for (int mf = 0; mf < 4; mf++) {
#pragma unroll
        for (int h = 0; h < 2; h++) {
            int r = rr + mf * 16 + h * 8;
            if (!SHARED) {
                if (r >= cnt) continue;
                int flat = g_tok[e][r] * 2 + g_slot[e][r];
                size_t base = (size_t)flat * HD;
#pragma unroll
                for (int nf = 0; nf < 4; nf++) {
                    size_t off = base + cc0 + nf * 8;
                    *(float2*)(g_dslot + off) =
                        make_float2(cc[mf][nf][h * 2 + 0], cc[mf][nf][h * 2 + 1]);
                }
            } else {
                float p0 = g_p[r][0], p1 = g_p[r][1];
                const float* d0 = g_dslot + (size_t)(2 * r) * HD;
                const float* d1 = d0 + HD;
#pragma unroll
                for (int nf = 0; nf < 4; nf++) {
                    int col = cc0 + nf * 8;
                    float2 v0 = *(const float2*)(d0 + col);
                    float2 v1 = *(const float2*)(d1 + col);
                    float2 o;
                    o.x = cc[mf][nf][h * 2 + 0] + p0 * v0.x + p1 * v1.x;
                    o.y = cc[mf][nf][h * 2 + 1] + p0 * v0.y + p1 * v1.y;
                    *(float2*)(Out + (size_t)r * HD + col) = o;
                }
            }
        }
    }
}

// =================== launch ===================
extern "C" void kernel_launch(void* const* d_in, const int* in_sizes, int n_in,
                              void* d_out, int out_size) {
    const float* x      = (const float*)d_in[0];
    const float* gate_w = (const float*)d_in[1];
    const float* Wg     = (const float*)d_in[2];
    const float* Wu     = (const float*)d_in[3];
    const float* Wd     = (const float*)d_in[4];
    const float* Sg     = (const float*)d_in[5];
    const float* Su     = (const float*)d_in[6];
    const float* Sd     = (const float*)d_in[7];
    float* out = (float*)d_out;

    const int SMEM = 2 * 65536 + 128;
    cudaFuncSetAttribute(gateup_hmma<false>, cudaFuncAttributeMaxDynamicSharedMemorySize, SMEM);
    cudaFuncSetAttribute(gateup_hmma<true>,  cudaFuncAttributeMaxDynamicSharedMemorySize, SMEM);
    cudaFuncSetAttribute(down_hmma<false>,   cudaFuncAttributeMaxDynamicSharedMemorySize, SMEM);
    cudaFuncSetAttribute(down_hmma<true>,    cudaFuncAttributeMaxDynamicSharedMemorySize, SMEM);

    // split all fp32 operands into bf16 hi/lo
    auto launch_split = [&](const float* src, int sel, size_t n) {
        int n4 = (int)(n / 4);
        int grid = (n4 + 255) / 256;
        split_kernel<<<grid, 256>>>((const float4*)src, sel, n4);
    };
    launch_split(Wg, 0, (size_t)NE * HD * ID);
    launch_split(Wu, 1, (size_t)NE * HD * ID);
    launch_split(Wd, 2, (size_t)NE * ID * HD);
    launch_split(Sg, 3, (size_t)HD * ISD);
    launch_split(Su, 4, (size_t)HD * ISD);
    launch_split(Sd, 5, (size_t)ISD * HD);
    launch_split(x,  6, (size_t)TT * HD);

    zero_counts_kernel<<<1, 32>>>();
    router_kernel<<<TT / 256, 256>>>(x, gate_w);

    dim3 gGU(TT / 128, ID / 64, NE);        // 16 x 44 x 8 (early exit on cnt)
    gateup_hmma<false><<<gGU, 256, SMEM>>>();

    dim3 gSGU(TT / 128, ISD / 64);          // 16 x 22
    gateup_hmma<true><<<gSGU, 256, SMEM>>>();

    dim3 gD(TT / 128, HD / 128, NE);        // 16 x 8 x 8
    down_hmma<false><<<gD, 256, SMEM>>>(nullptr);

    dim3 gSD(TT / 128, HD / 128);           // 16 x 8
    down_hmma<true><<<gSD, 256, SMEM>>>(out);
}

// round 5
// speedup vs baseline: 3.0255x; 1.2667x over previous
#include <cuda_runtime.h>
#include <cuda_fp16.h>
#include <math.h>

#define TT   2048
#define HD   1024
#define ID   2816
#define NE   8
#define ISD  1408

// ---- routing scratch ----
__device__ int   g_count[NE];
__device__ int   g_tok[NE][TT];
__device__ int   g_slot[NE][TT];
__device__ float g_p[TT][2];
__device__ float g_dslot[(size_t)TT * 2 * HD];

// ---- fp16 operands (B single copy; A hi/lo split) ----
__device__ __half g_Wg16[(size_t)NE * HD * ID];
__device__ __half g_Wu16[(size_t)NE * HD * ID];
__device__ __half g_Wd16[(size_t)NE * ID * HD];
__device__ __half g_Sg16[(size_t)HD * ISD];
__device__ __half g_Su16[(size_t)HD * ISD];
__device__ __half g_Sd16[(size_t)ISD * HD];
__device__ __half g_xhi[(size_t)TT * HD];
__device__ __half g_xlo[(size_t)TT * HD];
__device__ __half g_acthi[(size_t)TT * 2 * ID];
__device__ __half g_actlo[(size_t)TT * 2 * ID];
__device__ __half g_shacthi[(size_t)TT * ISD];
__device__ __half g_shactlo[(size_t)TT * ISD];

// =================== helpers ===================
__device__ __forceinline__ unsigned s2u(const void* p) {
    return (unsigned)__cvta_generic_to_shared(p);
}
__device__ __forceinline__ unsigned swz(unsigned o) { return o ^ ((o >> 3) & 0x70); }

__device__ __forceinline__ void split2h(float f0, float f1, unsigned& hi, unsigned& lo) {
    __half h0 = __float2half_rn(f0);
    __half h1 = __float2half_rn(f1);
    __half l0 = __float2half_rn(f0 - __half2float(h0));
    __half l1 = __float2half_rn(f1 - __half2float(h1));
    hi = (unsigned)__half_as_ushort(h0) | ((unsigned)__half_as_ushort(h1) << 16);
    lo = (unsigned)__half_as_ushort(l0) | ((unsigned)__half_as_ushort(l1) << 16);
}
__device__ __forceinline__ unsigned pack2h(float f0, float f1) {
    __half2 h = __floats2half2_rn(f0, f1);
    return *(unsigned*)&h;
}

__device__ __forceinline__ void sts128(unsigned a, uint4 v) {
    asm volatile("st.shared.v4.b32 [%0], {%1,%2,%3,%4};"
                 :: "r"(a), "r"(v.x), "r"(v.y), "r"(v.z), "r"(v.w));
}
__device__ __forceinline__ void ldsm4(unsigned a, unsigned* r) {
    asm volatile("ldmatrix.sync.aligned.m8n8.x4.shared.b16 {%0,%1,%2,%3}, [%4];"
                 : "=r"(r[0]), "=r"(r[1]), "=r"(r[2]), "=r"(r[3]) : "r"(a));
}
__device__ __forceinline__ void ldsm4t(unsigned a, unsigned* r) {
    asm volatile("ldmatrix.sync.aligned.m8n8.x4.trans.shared.b16 {%0,%1,%2,%3}, [%4];"
                 : "=r"(r[0]), "=r"(r[1]), "=r"(r[2]), "=r"(r[3]) : "r"(a));
}
__device__ __forceinline__ void mma16816(float* c, const unsigned* a, const unsigned* b) {
    asm volatile("mma.sync.aligned.m16n8k16.row.col.f32.f16.f16.f32 "
                 "{%0,%1,%2,%3}, {%4,%5,%6,%7}, {%8,%9}, {%0,%1,%2,%3};"
                 : "+f"(c[0]), "+f"(c[1]), "+f"(c[2]), "+f"(c[3])
                 : "r"(a[0]), "r"(a[1]), "r"(a[2]), "r"(a[3]), "r"(b[0]), "r"(b[1]));
}
__device__ __forceinline__ float silu_mul(float g, float u) {
    return u * g / (1.f + __expf(-g));
}

// =================== converters ===================
// weights: fp32 -> single fp16 copy (rn). 8 floats -> uint4 per thread.
__global__ void conv_kernel(const float4* __restrict__ src, int sel, int n8) {
    __half* dst;
    switch (sel) {
        case 0: dst = g_Wg16; break;
        case 1: dst = g_Wu16; break;
        case 2: dst = g_Wd16; break;
        case 3: dst = g_Sg16; break;
        case 4: dst = g_Su16; break;
        default: dst = g_Sd16; break;
    }
    int i = blockIdx.x * blockDim.x + threadIdx.x;
    if (i >= n8) return;
    float4 a = src[2 * i], b = src[2 * i + 1];
    uint4 o;
    o.x = pack2h(a.x, a.y);
    o.y = pack2h(a.z, a.w);
    o.z = pack2h(b.x, b.y);
    o.w = pack2h(b.z, b.w);
    ((uint4*)dst)[i] = o;
}

// x: fp32 -> fp16 hi/lo split
__global__ void splitx_kernel(const float4* __restrict__ src, int n4) {
    int i = blockIdx.x * blockDim.x + threadIdx.x;
    if (i >= n4) return;
    float4 v = src[i];
    unsigned h0, l0, h1, l1;
    split2h(v.x, v.y, h0, l0);
    split2h(v.z, v.w, h1, l1);
    ((uint2*)g_xhi)[i] = make_uint2(h0, h1);
    ((uint2*)g_xlo)[i] = make_uint2(l0, l1);
}

// =================== router ===================
__global__ void zero_counts_kernel() { if (threadIdx.x < NE) g_count[threadIdx.x] = 0; }

__global__ void router_kernel(const float* __restrict__ x, const float* __restrict__ gw) {
    int t = blockIdx.x * blockDim.x + threadIdx.x;
    if (t >= TT) return;
    float lg[NE];
#pragma unroll
    for (int e = 0; e < NE; e++) lg[e] = 0.f;
    const float* xr = x + (size_t)t * HD;
    for (int h = 0; h < HD; h++) {
        float xv = xr[h];
#pragma unroll
        for (int e = 0; e < NE; e++) lg[e] = fmaf(xv, gw[h * NE + e], lg[e]);
    }
    int i0 = 0; float v0 = lg[0];
#pragma unroll
    for (int e = 1; e < NE; e++) if (lg[e] > v0) { v0 = lg[e]; i0 = e; }
    int i1 = -1; float v1 = -INFINITY;
#pragma unroll
    for (int e = 0; e < NE; e++) if (e != i0 && lg[e] > v1) { v1 = lg[e]; i1 = e; }
    float e1 = expf(v1 - v0);
    float inv = 1.f / (1.f + e1);
    g_p[t][0] = inv;
    g_p[t][1] = e1 * inv;
    int p0 = atomicAdd(&g_count[i0], 1);
    g_tok[i0][p0] = t; g_slot[i0][p0] = 0;
    int p1 = atomicAdd(&g_count[i1], 1);
    g_tok[i1][p1] = t; g_slot[i1][p1] = 1;
}

// =================== gate+up HMMA (BM=128, BN=64, BK=64) ===================
// smem/stage: A hi 16K | A lo 16K | Bg 8K | Bu 8K = 48K
#define GU_AH  0u
#define GU_AL  16384u
#define GU_BG  32768u
#define GU_BU  40960u
#define BUFSZ  49152u

template<bool SHARED>
__global__ void __launch_bounds__(256, 1) gateup_hmma() {
    constexpr int K_TOT = HD;
    constexpr int N_TOT = SHARED ? ISD : ID;
    constexpr int NK = K_TOT / 64;
    const int tid = threadIdx.x, l = tid & 31, wid = tid >> 5;
    const int m0 = blockIdx.x * 128, n0 = blockIdx.y * 64;
    const int e = SHARED ? 0 : blockIdx.z;
    int cnt = TT;
    if (!SHARED) { cnt = g_count[e]; if (m0 >= cnt) return; }

    const __half* Bg = (SHARED ? g_Sg16 : g_Wg16 + (size_t)e * K_TOT * N_TOT) + n0;
    const __half* Bu = (SHARED ? g_Su16 : g_Wu16 + (size_t)e * K_TOT * N_TOT) + n0;
    __half* Ohi = SHARED ? g_shacthi : g_acthi;
    __half* Olo = SHARED ? g_shactlo : g_actlo;

    size_t aoff[4];
#pragma unroll
    for (int p = 0; p < 4; p++) {
        int idx = m0 + p * 32 + (tid >> 3);
        if (!SHARED) {
            int ci = idx < cnt ? idx : cnt - 1;
            aoff[p] = (size_t)g_tok[e][ci] * HD;
        } else {
            aoff[p] = (size_t)idx * HD;
        }
    }

    extern __shared__ char dyn[];
    unsigned sb = (s2u(dyn) + 127) & ~127u;

    auto LDG = [&](int kt, uint4* ra, uint4* rb) {
        int k0 = kt * 64;
#pragma unroll
        for (int p = 0; p < 4; p++) {
            size_t o = aoff[p] + k0 + (tid & 7) * 8;
            ra[2 * p + 0] = *(const uint4*)(g_xhi + o);
            ra[2 * p + 1] = *(const uint4*)(g_xlo + o);
        }
#pragma unroll
        for (int p = 0; p < 2; p++) {
            int s = p * 256 + tid;
            size_t o = (size_t)(k0 + (s >> 3)) * N_TOT + (s & 7) * 8;
            rb[p * 2 + 0] = *(const uint4*)(Bg + o);
            rb[p * 2 + 1] = *(const uint4*)(Bu + o);
        }
    };
    auto STS = [&](int st, uint4* ra, uint4* rb) {
        unsigned bb = sb + st * BUFSZ;
#pragma unroll
        for (int p = 0; p < 4; p++) {
            unsigned d = swz((p * 32 + (tid >> 3)) * 128 + (tid & 7) * 16);
            sts128(bb + GU_AH + d, ra[2 * p + 0]);
            sts128(bb + GU_AL + d, ra[2 * p + 1]);
        }
#pragma unroll
        for (int p = 0; p < 2; p++) {
            int s = p * 256 + tid;
            unsigned d = swz((s >> 3) * 128 + (s & 7) * 16);
            sts128(bb + GU_BG + d, rb[p * 2 + 0]);
            sts128(bb + GU_BU + d, rb[p * 2 + 1]);
        }
    };

    float cg[4][2][4] = {}, cu[4][2][4] = {};
    const int wm = (wid & 1) * 64, wn = (wid >> 1) * 16;
    const unsigned aRowB = (unsigned)(wm + (l & 15)) * 128;
    const unsigned sx = l & 7;
    const unsigned aCx = (l >> 4) & 1;
    const unsigned bKr = (l & 7) + ((l >> 3) & 1) * 8;
    const unsigned bG2 = (l >> 4) & 1;
    const unsigned bCk = ((((unsigned)wn >> 3) + bG2) ^ sx) << 4;

    auto COMPUTE = [&](int st) {
        unsigned bb = sb + st * BUFSZ;
#pragma unroll
        for (int ks = 0; ks < 4; ks++) {
            unsigned cka = (((unsigned)(ks * 2) + aCx) ^ sx) << 4;
            unsigned ah[4][4], al[4][4];
#pragma unroll
            for (int mf = 0; mf < 4; mf++) {
                unsigned ad = bb + aRowB + mf * 2048 + cka;
                ldsm4(ad + GU_AH, ah[mf]);
                ldsm4(ad + GU_AL, al[mf]);
            }
            unsigned brow = (unsigned)(ks * 16 + bKr) * 128 + bCk;
            unsigned bg[4], bu[4];
            ldsm4t(bb + GU_BG + brow, bg);
            ldsm4t(bb + GU_BU + brow, bu);
#pragma unroll
            for (int mf = 0; mf < 4; mf++)
#pragma unroll
                for (int nf = 0; nf < 2; nf++) {
                    mma16816(cg[mf][nf], ah[mf], bg + nf * 2);
                    mma16816(cg[mf][nf], al[mf], bg + nf * 2);
                    mma16816(cu[mf][nf], ah[mf], bu + nf * 2);
                    mma16816(cu[mf][nf], al[mf], bu + nf * 2);
                }
        }
    };

    uint4 ra[8], rb[4];
    LDG(0, ra, rb);
    STS(0, ra, rb);
#pragma unroll 1
    for (int kt = 0; kt < NK; kt++) {
        __syncthreads();
        if (kt + 1 < NK) LDG(kt + 1, ra, rb);
        COMPUTE(kt & 1);
        if (kt + 1 < NK) STS((kt + 1) & 1, ra, rb);
    }

    const int rr = m0 + wm + (l >> 2);
    const int cc0 = n0 + wn + (l & 3) * 2;
#pragma unroll
    for (int mf = 0; mf < 4; mf++) {
#pragma unroll
        for (int h = 0; h < 2; h++) {
            int r = rr + mf * 16 + h * 8;
            size_t obase;
            if (!SHARED) {
                if (r >= cnt) continue;
                int flat = g_tok[e][r] * 2 + g_slot[e][r];
                obase = (size_t)flat * N_TOT;
            } else {
                obase = (size_t)r * N_TOT;
            }
#pragma unroll
            for (int nf = 0; nf < 2; nf++) {
                float a0 = silu_mul(cg[mf][nf][h * 2 + 0], cu[mf][nf][h * 2 + 0]);
                float a1 = silu_mul(cg[mf][nf][h * 2 + 1], cu[mf][nf][h * 2 + 1]);
                unsigned hi, lo;
                split2h(a0, a1, hi, lo);
                size_t off = obase + cc0 + nf * 8;
                *(unsigned*)(Ohi + off) = hi;
                *(unsigned*)(Olo + off) = lo;
            }
        }
    }
}

// =================== down HMMA (BM=128, BN=128, BK=64) ===================
// smem/stage: A hi 16K | A lo 16K | B 16K = 48K
#define DN_AH 0u
#define DN_AL 16384u
#define DN_B  32768u

template<bool SHARED>
__global__ void __launch_bounds__(256, 1) down_hmma(float* __restrict__ Out) {
    constexpr int K_TOT = SHARED ? ISD : ID;
    constexpr int NK = K_TOT / 64;
    const int tid = threadIdx.x, l = tid & 31, wid = tid >> 5;
    const int m0 = blockIdx.x * 128, n0 = blockIdx.y * 128;
    const int e = SHARED ? 0 : blockIdx.z;
    int cnt = TT;
    if (!SHARED) { cnt = g_count[e]; if (m0 >= cnt) return; }

    const __half* B = (SHARED ? g_Sd16 : g_Wd16 + (size_t)e * K_TOT * HD) + n0;
    const __half* Ahi = SHARED ? g_shacthi : g_acthi;
    const __half* Alo = SHARED ? g_shactlo : g_actlo;

    size_t aoff[4];
#pragma unroll
    for (int p = 0; p < 4; p++) {
        int idx = m0 + p * 32 + (tid >> 3);
        if (!SHARED) {
            int ci = idx < cnt ? idx : cnt - 1;
            aoff[p] = (size_t)(g_tok[e][ci] * 2 + g_slot[e][ci]) * K_TOT;
        } else {
            aoff[p] = (size_t)idx * K_TOT;
        }
    }

    extern __shared__ char dyn[];
    unsigned sb = (s2u(dyn) + 127) & ~127u;

    auto LDG = [&](int kt, uint4* ra, uint4* rb) {
        int k0 = kt * 64;
#pragma unroll
        for (int p = 0; p < 4; p++) {
            size_t o = aoff[p] + k0 + (tid & 7) * 8;
            ra[2 * p + 0] = *(const uint4*)(Ahi + o);
            ra[2 * p + 1] = *(const uint4*)(Alo + o);
        }
#pragma unroll
        for (int p = 0; p < 4; p++) {
            int s = p * 256 + tid;
            size_t o = (size_t)(k0 + (s >> 4)) * HD + (s & 15) * 8;
            rb[p] = *(const uint4*)(B + o);
        }
    };
    auto STS = [&](int st, uint4* ra, uint4* rb) {
        unsigned bb = sb + st * BUFSZ;
#pragma unroll
        for (int p = 0; p < 4; p++) {
            unsigned d = swz((p * 32 + (tid >> 3)) * 128 + (tid & 7) * 16);
            sts128(bb + DN_AH + d, ra[2 * p + 0]);
            sts128(bb + DN_AL + d, ra[2 * p + 1]);
        }
#pragma unroll
        for (int p = 0; p < 4; p++) {
            int s = p * 256 + tid;
            int kk = s >> 4, c16 = s & 15;
            unsigned d = (unsigned)(c16 >> 3) * 8192 + swz(kk * 128 + (c16 & 7) * 16);
            sts128(bb + DN_B + d, rb[p]);
        }
    };

    float cc[4][4][4] = {};
    const int wm = (wid & 1) * 64, wn = (wid >> 1) * 32;
    const unsigned aRowB = (unsigned)(wm + (l & 15)) * 128;
    const unsigned sx = l & 7;
    const unsigned aCx = (l >> 4) & 1;
    const unsigned bKr = (l & 7) + ((l >> 3) & 1) * 8;
    const unsigned bG2 = (l >> 4) & 1;
    const unsigned hoff = (unsigned)(wn >> 6) * 8192;
    const unsigned nq = ((unsigned)wn & 63) >> 3;
    const unsigned ck0 = ((nq + 0 + bG2) ^ sx) << 4;
    const unsigned ck1 = ((nq + 2 + bG2) ^ sx) << 4;

    auto COMPUTE = [&](int st) {
        unsigned bb = sb + st * BUFSZ;
#pragma unroll
        for (int ks = 0; ks < 4; ks++) {
            unsigned cka = (((unsigned)(ks * 2) + aCx) ^ sx) << 4;
            unsigned ah[4][4], al[4][4];
#pragma unroll
            for (int mf = 0; mf < 4; mf++) {
                unsigned ad = bb + aRowB + mf * 2048 + cka;
                ldsm4(ad + DN_AH, ah[mf]);
                ldsm4(ad + DN_AL, al[mf]);
            }
            unsigned brow = (unsigned)(ks * 16 + bKr) * 128;
            unsigned bh[8];
            ldsm4t(bb + DN_B + hoff + brow + ck0, bh);
            ldsm4t(bb + DN_B + hoff + brow + ck1, bh + 4);
#pragma unroll
            for (int mf = 0; mf < 4; mf++)
#pragma unroll
                for (int nf = 0; nf < 4; nf++) {
                    mma16816(cc[mf][nf], ah[mf], bh + nf * 2);
                    mma16816(cc[mf][nf], al[mf], bh + nf * 2);
                }
        }
    };

    uint4 ra[8], rb[4];
    LDG(0, ra, rb);
    STS(0, ra, rb);
#pragma unroll 1
    for (int kt = 0; kt < NK; kt++) {
        __syncthreads();
        if (kt + 1 < NK) LDG(kt + 1, ra, rb);
        COMPUTE(kt & 1);
        if (kt + 1 < NK) STS((kt + 1) & 1, ra, rb);
    }

    const int rr = m0 + wm + (l >> 2);
    const int cc0 = n0 + wn + (l & 3) * 2;
#pragma unroll
    for (int mf = 0; mf < 4; mf++) {
#pragma unroll
        for (int h = 0; h < 2; h++) {
            int r = rr + mf * 16 + h * 8;
            if (!SHARED) {
                if (r >= cnt) continue;
                int flat = g_tok[e][r] * 2 + g_slot[e][r];
                size_t base = (size_t)flat * HD;
#pragma unroll
                for (int nf = 0; nf < 4; nf++) {
                    size_t off = base + cc0 + nf * 8;
                    *(float2*)(g_dslot + off) =
                        make_float2(cc[mf][nf][h * 2 + 0], cc[mf][nf][h * 2 + 1]);
                }
            } else {
                float p0 = g_p[r][0], p1 = g_p[r][1];
                const float* d0 = g_dslot + (size_t)(2 * r) * HD;
                const float* d1 = d0 + HD;
#pragma unroll
                for (int nf = 0; nf < 4; nf++) {
                    int col = cc0 + nf * 8;
                    float2 v0 = *(const float2*)(d0 + col);
                    float2 v1 = *(const float2*)(d1 + col);
                    float2 o;
                    o.x = cc[mf][nf][h * 2 + 0] + p0 * v0.x + p1 * v1.x;
                    o.y = cc[mf][nf][h * 2 + 1] + p0 * v0.y + p1 * v1.y;
                    *(float2*)(Out + (size_t)r * HD + col) = o;
                }
            }
        }
    }
}

// =================== launch ===================
extern "C" void kernel_launch(void* const* d_in, const int* in_sizes, int n_in,
                              void* d_out, int out_size) {
    const float* x      = (const float*)d_in[0];
    const float* gate_w = (const float*)d_in[1];
    const float* Wg     = (const float*)d_in[2];
    const float* Wu     = (const float*)d_in[3];
    const float* Wd     = (const float*)d_in[4];
    const float* Sg     = (const float*)d_in[5];
    const float* Su     = (const float*)d_in[6];
    const float* Sd     = (const float*)d_in[7];
    float* out = (float*)d_out;

    const int SMEM = 2 * 49152 + 128;
    cudaFuncSetAttribute(gateup_hmma<false>, cudaFuncAttributeMaxDynamicSharedMemorySize, SMEM);
    cudaFuncSetAttribute(gateup_hmma<true>,  cudaFuncAttributeMaxDynamicSharedMemorySize, SMEM);
    cudaFuncSetAttribute(down_hmma<false>,   cudaFuncAttributeMaxDynamicSharedMemorySize, SMEM);
    cudaFuncSetAttribute(down_hmma<true>,    cudaFuncAttributeMaxDynamicSharedMemorySize, SMEM);

    auto conv = [&](const float* src, int sel, size_t n) {
        int n8 = (int)(n / 8);
        conv_kernel<<<(n8 + 255) / 256, 256>>>((const float4*)src, sel, n8);
    };

    // Launch order puts gateup_hmma<false> 6th so ncu (-s 5 -c 1) profiles it.
    zero_counts_kernel<<<1, 32>>>();                                   // 1
    router_kernel<<<TT / 256, 256>>>(x, gate_w);                       // 2
    {
        int n4 = TT * HD / 4;
        splitx_kernel<<<(n4 + 255) / 256, 256>>>((const float4*)x, n4); // 3
    }
    conv(Wg, 0, (size_t)NE * HD * ID);                                  // 4
    conv(Wu, 1, (size_t)NE * HD * ID);                                  // 5

    dim3 gGU(TT / 128, ID / 64, NE);
    gateup_hmma<false><<<gGU, 256, SMEM>>>();                           // 6 <- profiled

    conv(Sg, 3, (size_t)HD * ISD);
    conv(Su, 4, (size_t)HD * ISD);
    dim3 gSGU(TT / 128, ISD / 64);
    gateup_hmma<true><<<gSGU, 256, SMEM>>>();

    conv(Wd, 2, (size_t)NE * ID * HD);
    dim3 gD(TT / 128, HD / 128, NE);
    down_hmma<false><<<gD, 256, SMEM>>>(nullptr);

    conv(Sd, 5, (size_t)ISD * HD);
    dim3 gSD(TT / 128, HD / 128);
    down_hmma<true><<<gSD, 256, SMEM>>>(out);
}

// round 6
// speedup vs baseline: 3.3616x; 1.1111x over previous
#include <cuda_runtime.h>
#include <cuda_fp16.h>
#include <math.h>

#define TT   2048
#define HD   1024
#define ID   2816
#define NE   8
#define ISD  1408

// ---- routing scratch ----
__device__ int   g_count[NE];
__device__ int   g_tok[NE][TT];
__device__ int   g_slot[NE][TT];
__device__ float g_p[TT][2];
__device__ float g_dslot[(size_t)TT * 2 * HD];

// ---- fp16 operands ----
__device__ __half g_Wg16[(size_t)NE * HD * ID];
__device__ __half g_Wu16[(size_t)NE * HD * ID];
__device__ __half g_Wd16[(size_t)NE * ID * HD];
__device__ __half g_Sg16[(size_t)HD * ISD];
__device__ __half g_Su16[(size_t)HD * ISD];
__device__ __half g_Sd16[(size_t)ISD * HD];
__device__ __half g_xhi[(size_t)TT * HD];
__device__ __half g_xlo[(size_t)TT * HD];
__device__ __half g_act[(size_t)TT * 2 * ID];       // expert act: single fp16
__device__ __half g_shacthi[(size_t)TT * ISD];      // shared act: hi/lo
__device__ __half g_shactlo[(size_t)TT * ISD];

// =================== helpers ===================
__device__ __forceinline__ unsigned s2u(const void* p) {
    return (unsigned)__cvta_generic_to_shared(p);
}
__device__ __forceinline__ unsigned swz(unsigned o) { return o ^ ((o >> 3) & 0x70); }

__device__ __forceinline__ void split2h(float f0, float f1, unsigned& hi, unsigned& lo) {
    __half h0 = __float2half_rn(f0);
    __half h1 = __float2half_rn(f1);
    __half l0 = __float2half_rn(f0 - __half2float(h0));
    __half l1 = __float2half_rn(f1 - __half2float(h1));
    hi = (unsigned)__half_as_ushort(h0) | ((unsigned)__half_as_ushort(h1) << 16);
    lo = (unsigned)__half_as_ushort(l0) | ((unsigned)__half_as_ushort(l1) << 16);
}
__device__ __forceinline__ unsigned pack2h(float f0, float f1) {
    __half2 h = __floats2half2_rn(f0, f1);
    return *(unsigned*)&h;
}
__device__ __forceinline__ void cpasync16(unsigned s, const void* g) {
    asm volatile("cp.async.cg.shared.global [%0], [%1], 16;" :: "r"(s), "l"(g));
}
#define CP_COMMIT() asm volatile("cp.async.commit_group;" ::: "memory")
#define CP_WAIT1()  asm volatile("cp.async.wait_group 1;"  ::: "memory")
#define CP_WAIT0()  asm volatile("cp.async.wait_group 0;"  ::: "memory")

__device__ __forceinline__ void ldsm4(unsigned a, unsigned* r) {
    asm volatile("ldmatrix.sync.aligned.m8n8.x4.shared.b16 {%0,%1,%2,%3}, [%4];"
                 : "=r"(r[0]), "=r"(r[1]), "=r"(r[2]), "=r"(r[3]) : "r"(a));
}
__device__ __forceinline__ void ldsm4t(unsigned a, unsigned* r) {
    asm volatile("ldmatrix.sync.aligned.m8n8.x4.trans.shared.b16 {%0,%1,%2,%3}, [%4];"
                 : "=r"(r[0]), "=r"(r[1]), "=r"(r[2]), "=r"(r[3]) : "r"(a));
}
__device__ __forceinline__ void mma16816(float* c, const unsigned* a, const unsigned* b) {
    asm volatile("mma.sync.aligned.m16n8k16.row.col.f32.f16.f16.f32 "
                 "{%0,%1,%2,%3}, {%4,%5,%6,%7}, {%8,%9}, {%0,%1,%2,%3};"
                 : "+f"(c[0]), "+f"(c[1]), "+f"(c[2]), "+f"(c[3])
                 : "r"(a[0]), "r"(a[1]), "r"(a[2]), "r"(a[3]), "r"(b[0]), "r"(b[1]));
}
__device__ __forceinline__ float silu_mul(float g, float u) {
    return u * g / (1.f + __expf(-g));
}

// =================== converters ===================
__global__ void conv_kernel(const float4* __restrict__ src, int sel, int n8) {
    __half* dst;
    switch (sel) {
        case 0: dst = g_Wg16; break;
        case 1: dst = g_Wu16; break;
        case 2: dst = g_Wd16; break;
        case 3: dst = g_Sg16; break;
        case 4: dst = g_Su16; break;
        default: dst = g_Sd16; break;
    }
    int i = blockIdx.x * blockDim.x + threadIdx.x;
    if (i >= n8) return;
    float4 a = src[2 * i], b = src[2 * i + 1];
    uint4 o;
    o.x = pack2h(a.x, a.y);
    o.y = pack2h(a.z, a.w);
    o.z = pack2h(b.x, b.y);
    o.w = pack2h(b.z, b.w);
    ((uint4*)dst)[i] = o;
}

__global__ void splitx_kernel(const float4* __restrict__ src, int n4) {
    int i = blockIdx.x * blockDim.x + threadIdx.x;
    if (i >= n4) return;
    float4 v = src[i];
    unsigned h0, l0, h1, l1;
    split2h(v.x, v.y, h0, l0);
    split2h(v.z, v.w, h1, l1);
    ((uint2*)g_xhi)[i] = make_uint2(h0, h1);
    ((uint2*)g_xlo)[i] = make_uint2(l0, l1);
}

// =================== router ===================
__global__ void zero_counts_kernel() { if (threadIdx.x < NE) g_count[threadIdx.x] = 0; }

__global__ void router_kernel(const float* __restrict__ x, const float* __restrict__ gw) {
    int t = blockIdx.x * blockDim.x + threadIdx.x;
    if (t >= TT) return;
    float lg[NE];
#pragma unroll
    for (int e = 0; e < NE; e++) lg[e] = 0.f;
    const float* xr = x + (size_t)t * HD;
    for (int h = 0; h < HD; h++) {
        float xv = xr[h];
#pragma unroll
        for (int e = 0; e < NE; e++) lg[e] = fmaf(xv, gw[h * NE + e], lg[e]);
    }
    int i0 = 0; float v0 = lg[0];
#pragma unroll
    for (int e = 1; e < NE; e++) if (lg[e] > v0) { v0 = lg[e]; i0 = e; }
    int i1 = -1; float v1 = -INFINITY;
#pragma unroll
    for (int e = 0; e < NE; e++) if (e != i0 && lg[e] > v1) { v1 = lg[e]; i1 = e; }
    float e1 = expf(v1 - v0);
    float inv = 1.f / (1.f + e1);
    g_p[t][0] = inv;
    g_p[t][1] = e1 * inv;
    int p0 = atomicAdd(&g_count[i0], 1);
    g_tok[i0][p0] = t; g_slot[i0][p0] = 0;
    int p1 = atomicAdd(&g_count[i1], 1);
    g_tok[i1][p1] = t; g_slot[i1][p1] = 1;
}

// =================== gate+up HMMA (BM=128, BN=128, BK=64, warp 64x32) ===================
// stage: A hi 16K | A lo 16K | Bg 16K | Bu 16K = 64K
#define GU_AH 0u
#define GU_AL 16384u
#define GU_BG 32768u
#define GU_BU 49152u
#define GU_STG 65536u

template<bool SHARED>
__global__ void __launch_bounds__(256, 1) gateup_hmma() {
    constexpr int K_TOT = HD;
    constexpr int N_TOT = SHARED ? ISD : ID;
    constexpr int NK = K_TOT / 64;
    const int tid = threadIdx.x, l = tid & 31, wid = tid >> 5;
    const int m0 = blockIdx.x * 128, n0 = blockIdx.y * 128;
    const int e = SHARED ? 0 : blockIdx.z;
    int cnt = TT;
    if (!SHARED) { cnt = g_count[e]; if (m0 >= cnt) return; }

    const __half* Bg = (SHARED ? g_Sg16 : g_Wg16 + (size_t)e * K_TOT * N_TOT) + n0;
    const __half* Bu = (SHARED ? g_Su16 : g_Wu16 + (size_t)e * K_TOT * N_TOT) + n0;

    size_t aoff[4];
#pragma unroll
    for (int p = 0; p < 4; p++) {
        int idx = m0 + p * 32 + (tid >> 3);
        if (!SHARED) {
            int ci = idx < cnt ? idx : cnt - 1;
            aoff[p] = (size_t)g_tok[e][ci] * HD;
        } else {
            aoff[p] = (size_t)idx * HD;
        }
    }

    extern __shared__ char dyn[];
    unsigned sb = (s2u(dyn) + 127) & ~127u;
    const int kseg = tid & 7;

    auto LOAD = [&](int kt) {
        unsigned bb = sb + (kt & 1) * GU_STG;
        int k0 = kt * 64;
#pragma unroll
        for (int i = 0; i < 4; i++) {
            unsigned d = swz((unsigned)(i * 32 + (tid >> 3)) * 128 + kseg * 16);
            cpasync16(bb + GU_AH + d, g_xhi + aoff[i] + k0 + kseg * 8);
            cpasync16(bb + GU_AL + d, g_xlo + aoff[i] + k0 + kseg * 8);
        }
#pragma unroll
        for (int i = 0; i < 4; i++) {
            int s = i * 256 + tid;
            int kk = s >> 4, c16 = s & 15;
            unsigned d = (unsigned)(c16 >> 3) * 8192 + swz((unsigned)kk * 128 + (c16 & 7) * 16);
            size_t o = (size_t)(k0 + kk) * N_TOT + c16 * 8;
            cpasync16(bb + GU_BG + d, Bg + o);
            cpasync16(bb + GU_BU + d, Bu + o);
        }
        CP_COMMIT();
    };

    float cg[4][4][4] = {}, cu[4][4][4] = {};
    const int wm = (wid & 1) * 64, wn = (wid >> 1) * 32;
    const unsigned aRowB = (unsigned)(wm + (l & 15)) * 128;
    const unsigned sx = l & 7;
    const unsigned aCx = (l >> 4) & 1;
    const unsigned bKr = (l & 7) + ((l >> 3) & 1) * 8;
    const unsigned bG2 = (l >> 4) & 1;
    const unsigned hoff = (unsigned)(wn >> 6) * 8192;
    const unsigned nq = ((unsigned)wn & 63) >> 3;
    const unsigned ck0 = ((nq + 0 + bG2) ^ sx) << 4;
    const unsigned ck1 = ((nq + 2 + bG2) ^ sx) << 4;

    auto COMPUTE = [&](int st) {
        unsigned bb = sb + st * GU_STG;
#pragma unroll
        for (int ks = 0; ks < 4; ks++) {
            unsigned cka = (((unsigned)(ks * 2) + aCx) ^ sx) << 4;
            unsigned ah[4][4], al[4][4];
#pragma unroll
            for (int mf = 0; mf < 4; mf++) {
                unsigned ad = bb + aRowB + mf * 2048 + cka;
                ldsm4(ad + GU_AH, ah[mf]);
                ldsm4(ad + GU_AL, al[mf]);
            }
            unsigned brow = (unsigned)(ks * 16 + bKr) * 128;
            unsigned bg[8], bu[8];
            ldsm4t(bb + GU_BG + hoff + brow + ck0, bg);
            ldsm4t(bb + GU_BG + hoff + brow + ck1, bg + 4);
            ldsm4t(bb + GU_BU + hoff + brow + ck0, bu);
            ldsm4t(bb + GU_BU + hoff + brow + ck1, bu + 4);
#pragma unroll
            for (int mf = 0; mf < 4; mf++)
#pragma unroll
                for (int nf = 0; nf < 4; nf++) {
                    mma16816(cg[mf][nf], ah[mf], bg + nf * 2);
                    mma16816(cg[mf][nf], al[mf], bg + nf * 2);
                    mma16816(cu[mf][nf], ah[mf], bu + nf * 2);
                    mma16816(cu[mf][nf], al[mf], bu + nf * 2);
                }
        }
    };

    LOAD(0);
#pragma unroll 1
    for (int kt = 0; kt < NK; kt++) {
        if (kt + 1 < NK) { LOAD(kt + 1); CP_WAIT1(); } else { CP_WAIT0(); }
        __syncthreads();
        COMPUTE(kt & 1);
        __syncthreads();
    }

    const int rr = m0 + wm + (l >> 2);
    const int cc0 = n0 + wn + (l & 3) * 2;
#pragma unroll
    for (int mf = 0; mf < 4; mf++) {
#pragma unroll
        for (int h = 0; h < 2; h++) {
            int r = rr + mf * 16 + h * 8;
            if (!SHARED) {
                if (r >= cnt) continue;
                int flat = g_tok[e][r] * 2 + g_slot[e][r];
                size_t obase = (size_t)flat * N_TOT;
#pragma unroll
                for (int nf = 0; nf < 4; nf++) {
                    float a0 = silu_mul(cg[mf][nf][h * 2 + 0], cu[mf][nf][h * 2 + 0]);
                    float a1 = silu_mul(cg[mf][nf][h * 2 + 1], cu[mf][nf][h * 2 + 1]);
                    *(unsigned*)(g_act + obase + cc0 + nf * 8) = pack2h(a0, a1);
                }
            } else {
                size_t obase = (size_t)r * N_TOT;
#pragma unroll
                for (int nf = 0; nf < 4; nf++) {
                    float a0 = silu_mul(cg[mf][nf][h * 2 + 0], cu[mf][nf][h * 2 + 0]);
                    float a1 = silu_mul(cg[mf][nf][h * 2 + 1], cu[mf][nf][h * 2 + 1]);
                    unsigned hi, lo;
                    split2h(a0, a1, hi, lo);
                    *(unsigned*)(g_shacthi + obase + cc0 + nf * 8) = hi;
                    *(unsigned*)(g_shactlo + obase + cc0 + nf * 8) = lo;
                }
            }
        }
    }
}

// =================== down HMMA (BM=128, BN=128, BK=64, warp 64x32) ===================
// expert: 1-term A (fp16), stage = A 16K | B 16K = 32K
// shared: 2-term A, stage = A hi 16K | A lo 16K | B 16K = 48K
template<bool SHARED>
__global__ void __launch_bounds__(256, 1) down_hmma(float* __restrict__ Out) {
    constexpr int K_TOT = SHARED ? ISD : ID;
    constexpr int NK = K_TOT / 64;
    constexpr unsigned AH = 0u;
    constexpr unsigned AL = 16384u;                      // shared only
    constexpr unsigned BB0 = SHARED ? 32768u : 16384u;
    constexpr unsigned STG = SHARED ? 49152u : 32768u;
    const int tid = threadIdx.x, l = tid & 31, wid = tid >> 5;
    const int m0 = blockIdx.x * 128, n0 = blockIdx.y * 128;
    const int e = SHARED ? 0 : blockIdx.z;
    int cnt = TT;
    if (!SHARED) { cnt = g_count[e]; if (m0 >= cnt) return; }

    const __half* B = (SHARED ? g_Sd16 : g_Wd16 + (size_t)e * K_TOT * HD) + n0;

    size_t aoff[4];
#pragma unroll
    for (int p = 0; p < 4; p++) {
        int idx = m0 + p * 32 + (tid >> 3);
        if (!SHARED) {
            int ci = idx < cnt ? idx : cnt - 1;
            aoff[p] = (size_t)(g_tok[e][ci] * 2 + g_slot[e][ci]) * K_TOT;
        } else {
            aoff[p] = (size_t)idx * K_TOT;
        }
    }

    extern __shared__ char dyn[];
    unsigned sb = (s2u(dyn) + 127) & ~127u;
    const int kseg = tid & 7;

    auto LOAD = [&](int kt) {
        unsigned bb = sb + (kt & 1) * STG;
        int k0 = kt * 64;
#pragma unroll
        for (int i = 0; i < 4; i++) {
            unsigned d = swz((unsigned)(i * 32 + (tid >> 3)) * 128 + kseg * 16);
            if (SHARED) {
                cpasync16(bb + AH + d, g_shacthi + aoff[i] + k0 + kseg * 8);
                cpasync16(bb + AL + d, g_shactlo + aoff[i] + k0 + kseg * 8);
            } else {
                cpasync16(bb + AH + d, g_act + aoff[i] + k0 + kseg * 8);
            }
        }
#pragma unroll
        for (int i = 0; i < 4; i++) {
            int s = i * 256 + tid;
            int kk = s >> 4, c16 = s & 15;
            unsigned d = (unsigned)(c16 >> 3) * 8192 + swz((unsigned)kk * 128 + (c16 & 7) * 16);
            cpasync16(bb + BB0 + d, B + (size_t)(k0 + kk) * HD + c16 * 8);
        }
        CP_COMMIT();
    };

    float cc[4][4][4] = {};
    const int wm = (wid & 1) * 64, wn = (wid >> 1) * 32;
    const unsigned aRowB = (unsigned)(wm + (l & 15)) * 128;
    const unsigned sx = l & 7;
    const unsigned aCx = (l >> 4) & 1;
    const unsigned bKr = (l & 7) + ((l >> 3) & 1) * 8;
    const unsigned bG2 = (l >> 4) & 1;
    const unsigned hoff = (unsigned)(wn >> 6) * 8192;
    const unsigned nq = ((unsigned)wn & 63) >> 3;
    const unsigned ck0 = ((nq + 0 + bG2) ^ sx) << 4;
    const unsigned ck1 = ((nq + 2 + bG2) ^ sx) << 4;

    auto COMPUTE = [&](int st) {
        unsigned bb = sb + st * STG;
#pragma unroll
        for (int ks = 0; ks < 4; ks++) {
            unsigned cka = (((unsigned)(ks * 2) + aCx) ^ sx) << 4;
            unsigned ah[4][4], al[4][4];
#pragma unroll
            for (int mf = 0; mf < 4; mf++) {
                unsigned ad = bb + aRowB + mf * 2048 + cka;
                ldsm4(ad + AH, ah[mf]);
                if (SHARED) ldsm4(ad + AL, al[mf]);
            }
            unsigned brow = (unsigned)(ks * 16 + bKr) * 128;
            unsigned bh[8];
            ldsm4t(bb + BB0 + hoff + brow + ck0, bh);
            ldsm4t(bb + BB0 + hoff + brow + ck1, bh + 4);
#pragma unroll
            for (int mf = 0; mf < 4; mf++)
#pragma unroll
                for (int nf = 0; nf < 4; nf++) {
                    mma16816(cc[mf][nf], ah[mf], bh + nf * 2);
                    if (SHARED) mma16816(cc[mf][nf], al[mf], bh + nf * 2);
                }
        }
    };

    LOAD(0);
#pragma unroll 1
    for (int kt = 0; kt < NK; kt++) {
        if (kt + 1 < NK) { LOAD(kt + 1); CP_WAIT1(); } else { CP_WAIT0(); }
        __syncthreads();
        COMPUTE(kt & 1);
        __syncthreads();
    }

    const int rr = m0 + wm + (l >> 2);
    const int cc0 = n0 + wn + (l & 3) * 2;
#pragma unroll
    for (int mf = 0; mf < 4; mf++) {
#pragma unroll
        for (int h = 0; h < 2; h++) {
            int r = rr + mf * 16 + h * 8;
            if (!SHARED) {
                if (r >= cnt) continue;
                int flat = g_tok[e][r] * 2 + g_slot[e][r];
                size_t base = (size_t)flat * HD;
#pragma unroll
                for (int nf = 0; nf < 4; nf++) {
                    size_t off = base + cc0 + nf * 8;
                    *(float2*)(g_dslot + off) =
                        make_float2(cc[mf][nf][h * 2 + 0], cc[mf][nf][h * 2 + 1]);
                }
            } else {
                float p0 = g_p[r][0], p1 = g_p[r][1];
                const float* d0 = g_dslot + (size_t)(2 * r) * HD;
                const float* d1 = d0 + HD;
#pragma unroll
                for (int nf = 0; nf < 4; nf++) {
                    int col = cc0 + nf * 8;
                    float2 v0 = *(const float2*)(d0 + col);
                    float2 v1 = *(const float2*)(d1 + col);
                    float2 o;
                    o.x = cc[mf][nf][h * 2 + 0] + p0 * v0.x + p1 * v1.x;
                    o.y = cc[mf][nf][h * 2 + 1] + p0 * v0.y + p1 * v1.y;
                    *(float2*)(Out + (size_t)r * HD + col) = o;
                }
            }
        }
    }
}

// =================== launch ===================
extern "C" void kernel_launch(void* const* d_in, const int* in_sizes, int n_in,
                              void* d_out, int out_size) {
    const float* x      = (const float*)d_in[0];
    const float* gate_w = (const float*)d_in[1];
    const float* Wg     = (const float*)d_in[2];
    const float* Wu     = (const float*)d_in[3];
    const float* Wd     = (const float*)d_in[4];
    const float* Sg     = (const float*)d_in[5];
    const float* Su     = (const float*)d_in[6];
    const float* Sd     = (const float*)d_in[7];
    float* out = (float*)d_out;

    cudaFuncSetAttribute(gateup_hmma<false>, cudaFuncAttributeMaxDynamicSharedMemorySize, 2 * 65536 + 128);
    cudaFuncSetAttribute(gateup_hmma<true>,  cudaFuncAttributeMaxDynamicSharedMemorySize, 2 * 65536 + 128);
    cudaFuncSetAttribute(down_hmma<false>,   cudaFuncAttributeMaxDynamicSharedMemorySize, 2 * 32768 + 128);
    cudaFuncSetAttribute(down_hmma<true>,    cudaFuncAttributeMaxDynamicSharedMemorySize, 2 * 49152 + 128);

    auto conv = [&](const float* src, int sel, size_t n) {
        int n8 = (int)(n / 8);
        conv_kernel<<<(n8 + 255) / 256, 256>>>((const float4*)src, sel, n8);
    };

    zero_counts_kernel<<<1, 32>>>();                                    // 1
    router_kernel<<<TT / 256, 256>>>(x, gate_w);                        // 2
    {
        int n4 = TT * HD / 4;
        splitx_kernel<<<(n4 + 255) / 256, 256>>>((const float4*)x, n4); // 3
    }
    conv(Wg, 0, (size_t)NE * HD * ID);                                  // 4
    conv(Wu, 1, (size_t)NE * HD * ID);                                  // 5

    dim3 gGU(TT / 128, ID / 128, NE);                                   // 16 x 22 x 8
    gateup_hmma<false><<<gGU, 256, 2 * 65536 + 128>>>();                // 6 <- profile target

    conv(Sg, 3, (size_t)HD * ISD);
    conv(Su, 4, (size_t)HD * ISD);
    dim3 gSGU(TT / 128, ISD / 128);                                     // 16 x 11
    gateup_hmma<true><<<gSGU, 256, 2 * 65536 + 128>>>();

    conv(Wd, 2, (size_t)NE * ID * HD);
    dim3 gD(TT / 128, HD / 128, NE);                                    // 16 x 8 x 8
    down_hmma<false><<<gD, 256, 2 * 32768 + 128>>>(nullptr);

    conv(Sd, 5, (size_t)ISD * HD);
    dim3 gSD(TT / 128, HD / 128);                                       // 16 x 8
    down_hmma<true><<<gSD, 256, 2 * 49152 + 128>>>(out);
}

// round 7
// speedup vs baseline: 4.1560x; 1.2363x over previous
#include <cuda_runtime.h>
#include <cuda_fp16.h>
#include <math.h>

#define TT   2048
#define HD   1024
#define ID   2816
#define NE   8
#define ISD  1408

// ---- routing scratch ----
__device__ int   g_count[NE];
__device__ int   g_tok[NE][TT];
__device__ int   g_slot[NE][TT];
__device__ float g_p[TT][2];
__device__ float g_dslot[(size_t)TT * 2 * HD];

// ---- fp16 operands ----
__device__ __half g_Wg16[(size_t)NE * HD * ID];
__device__ __half g_Wu16[(size_t)NE * HD * ID];
__device__ __half g_Wd16[(size_t)NE * ID * HD];
__device__ __half g_Sg16[(size_t)HD * ISD];
__device__ __half g_Su16[(size_t)HD * ISD];
__device__ __half g_Sd16[(size_t)ISD * HD];
__device__ __half g_x16[(size_t)TT * HD];
__device__ __half g_act[(size_t)TT * 2 * ID];       // expert act: single fp16
__device__ __half g_shacthi[(size_t)TT * ISD];      // shared act: hi/lo (accuracy hedge)
__device__ __half g_shactlo[(size_t)TT * ISD];

// =================== helpers ===================
__device__ __forceinline__ unsigned s2u(const void* p) {
    return (unsigned)__cvta_generic_to_shared(p);
}
__device__ __forceinline__ unsigned swz(unsigned o) { return o ^ ((o >> 3) & 0x70); }

__device__ __forceinline__ void split2h(float f0, float f1, unsigned& hi, unsigned& lo) {
    __half h0 = __float2half_rn(f0);
    __half h1 = __float2half_rn(f1);
    __half l0 = __float2half_rn(f0 - __half2float(h0));
    __half l1 = __float2half_rn(f1 - __half2float(h1));
    hi = (unsigned)__half_as_ushort(h0) | ((unsigned)__half_as_ushort(h1) << 16);
    lo = (unsigned)__half_as_ushort(l0) | ((unsigned)__half_as_ushort(l1) << 16);
}
__device__ __forceinline__ unsigned pack2h(float f0, float f1) {
    __half2 h = __floats2half2_rn(f0, f1);
    return *(unsigned*)&h;
}
__device__ __forceinline__ void cpasync16(unsigned s, const void* g) {
    asm volatile("cp.async.cg.shared.global [%0], [%1], 16;" :: "r"(s), "l"(g));
}
#define CP_COMMIT() asm volatile("cp.async.commit_group;" ::: "memory")
#define CP_WAIT1()  asm volatile("cp.async.wait_group 1;"  ::: "memory")
#define CP_WAIT0()  asm volatile("cp.async.wait_group 0;"  ::: "memory")

__device__ __forceinline__ void ldsm4(unsigned a, unsigned* r) {
    asm volatile("ldmatrix.sync.aligned.m8n8.x4.shared.b16 {%0,%1,%2,%3}, [%4];"
                 : "=r"(r[0]), "=r"(r[1]), "=r"(r[2]), "=r"(r[3]) : "r"(a));
}
__device__ __forceinline__ void ldsm4t(unsigned a, unsigned* r) {
    asm volatile("ldmatrix.sync.aligned.m8n8.x4.trans.shared.b16 {%0,%1,%2,%3}, [%4];"
                 : "=r"(r[0]), "=r"(r[1]), "=r"(r[2]), "=r"(r[3]) : "r"(a));
}
__device__ __forceinline__ void mma16816(float* c, const unsigned* a, const unsigned* b) {
    asm volatile("mma.sync.aligned.m16n8k16.row.col.f32.f16.f16.f32 "
                 "{%0,%1,%2,%3}, {%4,%5,%6,%7}, {%8,%9}, {%0,%1,%2,%3};"
                 : "+f"(c[0]), "+f"(c[1]), "+f"(c[2]), "+f"(c[3])
                 : "r"(a[0]), "r"(a[1]), "r"(a[2]), "r"(a[3]), "r"(b[0]), "r"(b[1]));
}
__device__ __forceinline__ float silu_mul(float g, float u) {
    return u * g / (1.f + __expf(-g));
}

// =================== converters ===================
__global__ void conv_kernel(const float4* __restrict__ src, int sel, int n8) {
    __half* dst;
    switch (sel) {
        case 0: dst = g_Wg16; break;
        case 1: dst = g_Wu16; break;
        case 2: dst = g_Wd16; break;
        case 3: dst = g_Sg16; break;
        case 4: dst = g_Su16; break;
        case 5: dst = g_Sd16; break;
        default: dst = g_x16; break;
    }
    int i = blockIdx.x * blockDim.x + threadIdx.x;
    if (i >= n8) return;
    float4 a = src[2 * i], b = src[2 * i + 1];
    uint4 o;
    o.x = pack2h(a.x, a.y);
    o.y = pack2h(a.z, a.w);
    o.z = pack2h(b.x, b.y);
    o.w = pack2h(b.z, b.w);
    ((uint4*)dst)[i] = o;
}

// =================== router ===================
__global__ void zero_counts_kernel() { if (threadIdx.x < NE) g_count[threadIdx.x] = 0; }

__global__ void router_kernel(const float* __restrict__ x, const float* __restrict__ gw) {
    int t = blockIdx.x * blockDim.x + threadIdx.x;
    if (t >= TT) return;
    float lg[NE];
#pragma unroll
    for (int e = 0; e < NE; e++) lg[e] = 0.f;
    const float* xr = x + (size_t)t * HD;
    for (int h = 0; h < HD; h++) {
        float xv = xr[h];
#pragma unroll
        for (int e = 0; e < NE; e++) lg[e] = fmaf(xv, gw[h * NE + e], lg[e]);
    }
    int i0 = 0; float v0 = lg[0];
#pragma unroll
    for (int e = 1; e < NE; e++) if (lg[e] > v0) { v0 = lg[e]; i0 = e; }
    int i1 = -1; float v1 = -INFINITY;
#pragma unroll
    for (int e = 0; e < NE; e++) if (e != i0 && lg[e] > v1) { v1 = lg[e]; i1 = e; }
    float e1 = expf(v1 - v0);
    float inv = 1.f / (1.f + e1);
    g_p[t][0] = inv;
    g_p[t][1] = e1 * inv;
    int p0 = atomicAdd(&g_count[i0], 1);
    g_tok[i0][p0] = t; g_slot[i0][p0] = 0;
    int p1 = atomicAdd(&g_count[i1], 1);
    g_tok[i1][p1] = t; g_slot[i1][p1] = 1;
}

// =================== gate+up HMMA (BM=128, BN=128, BK=64, 1-term A) ===================
// stage: A 16K | Bg 16K | Bu 16K = 48K; 3-stage ring
#define GU_A  0u
#define GU_BG 16384u
#define GU_BU 32768u
#define GU_STG 49152u

template<bool SHARED>
__global__ void __launch_bounds__(256, 1) gateup_hmma() {
    constexpr int K_TOT = HD;
    constexpr int N_TOT = SHARED ? ISD : ID;
    constexpr int NK = K_TOT / 64;
    const int tid = threadIdx.x, l = tid & 31, wid = tid >> 5;
    const int m0 = blockIdx.x * 128, n0 = blockIdx.y * 128;
    const int e = SHARED ? 0 : blockIdx.z;
    int cnt = TT;
    if (!SHARED) { cnt = g_count[e]; if (m0 >= cnt) return; }

    const __half* Bg = (SHARED ? g_Sg16 : g_Wg16 + (size_t)e * K_TOT * N_TOT) + n0;
    const __half* Bu = (SHARED ? g_Su16 : g_Wu16 + (size_t)e * K_TOT * N_TOT) + n0;

    size_t aoff[4];
#pragma unroll
    for (int p = 0; p < 4; p++) {
        int idx = m0 + p * 32 + (tid >> 3);
        if (!SHARED) {
            int ci = idx < cnt ? idx : cnt - 1;
            aoff[p] = (size_t)g_tok[e][ci] * HD;
        } else {
            aoff[p] = (size_t)idx * HD;
        }
    }

    extern __shared__ char dyn[];
    unsigned sb = (s2u(dyn) + 127) & ~127u;
    const int kseg = tid & 7;

    auto LOAD = [&](int kt) {
        unsigned bb = sb + (unsigned)(kt % 3) * GU_STG;
        int k0 = kt * 64;
#pragma unroll
        for (int i = 0; i < 4; i++) {
            unsigned d = swz((unsigned)(i * 32 + (tid >> 3)) * 128 + kseg * 16);
            cpasync16(bb + GU_A + d, g_x16 + aoff[i] + k0 + kseg * 8);
        }
#pragma unroll
        for (int i = 0; i < 4; i++) {
            int s = i * 256 + tid;
            int kk = s >> 4, c16 = s & 15;
            unsigned d = (unsigned)(c16 >> 3) * 8192 + swz((unsigned)kk * 128 + (c16 & 7) * 16);
            size_t o = (size_t)(k0 + kk) * N_TOT + c16 * 8;
            cpasync16(bb + GU_BG + d, Bg + o);
            cpasync16(bb + GU_BU + d, Bu + o);
        }
        CP_COMMIT();
    };

    float cg[4][4][4] = {}, cu[4][4][4] = {};
    const int wm = (wid & 1) * 64, wn = (wid >> 1) * 32;
    const unsigned aRowB = (unsigned)(wm + (l & 15)) * 128;
    const unsigned sx = l & 7;
    const unsigned aCx = (l >> 4) & 1;
    const unsigned bKr = (l & 7) + ((l >> 3) & 1) * 8;
    const unsigned bG2 = (l >> 4) & 1;
    const unsigned hoff = (unsigned)(wn >> 6) * 8192;
    const unsigned nq = ((unsigned)wn & 63) >> 3;
    const unsigned ck0 = ((nq + 0 + bG2) ^ sx) << 4;
    const unsigned ck1 = ((nq + 2 + bG2) ^ sx) << 4;

    auto COMPUTE = [&](int st) {
        unsigned bb = sb + (unsigned)st * GU_STG;
#pragma unroll
        for (int ks = 0; ks < 4; ks++) {
            unsigned cka = (((unsigned)(ks * 2) + aCx) ^ sx) << 4;
            unsigned ah[4][4];
#pragma unroll
            for (int mf = 0; mf < 4; mf++)
                ldsm4(bb + GU_A + aRowB + mf * 2048 + cka, ah[mf]);
            unsigned brow = (unsigned)(ks * 16 + bKr) * 128;
            unsigned bg[8], bu[8];
            ldsm4t(bb + GU_BG + hoff + brow + ck0, bg);
            ldsm4t(bb + GU_BG + hoff + brow + ck1, bg + 4);
            ldsm4t(bb + GU_BU + hoff + brow + ck0, bu);
            ldsm4t(bb + GU_BU + hoff + brow + ck1, bu + 4);
#pragma unroll
            for (int mf = 0; mf < 4; mf++)
#pragma unroll
                for (int nf = 0; nf < 4; nf++) {
                    mma16816(cg[mf][nf], ah[mf], bg + nf * 2);
                    mma16816(cu[mf][nf], ah[mf], bu + nf * 2);
                }
        }
    };

    LOAD(0);
    LOAD(1);
#pragma unroll 1
    for (int kt = 0; kt < NK; kt++) {
        if (kt + 1 < NK) CP_WAIT1(); else CP_WAIT0();
        __syncthreads();
        if (kt + 2 < NK) LOAD(kt + 2);
        COMPUTE(kt % 3);
    }

    const int rr = m0 + wm + (l >> 2);
    const int cc0 = n0 + wn + (l & 3) * 2;
#pragma unroll
    for (int mf = 0; mf < 4; mf++) {
#pragma unroll
        for (int h = 0; h < 2; h++) {
            int r = rr + mf * 16 + h * 8;
            if (!SHARED) {
                if (r >= cnt) continue;
                int flat = g_tok[e][r] * 2 + g_slot[e][r];
                size_t obase = (size_t)flat * N_TOT;
#pragma unroll
                for (int nf = 0; nf < 4; nf++) {
                    float a0 = silu_mul(cg[mf][nf][h * 2 + 0], cu[mf][nf][h * 2 + 0]);
                    float a1 = silu_mul(cg[mf][nf][h * 2 + 1], cu[mf][nf][h * 2 + 1]);
                    *(unsigned*)(g_act + obase + cc0 + nf * 8) = pack2h(a0, a1);
                }
            } else {
                size_t obase = (size_t)r * N_TOT;
#pragma unroll
                for (int nf = 0; nf < 4; nf++) {
                    float a0 = silu_mul(cg[mf][nf][h * 2 + 0], cu[mf][nf][h * 2 + 0]);
                    float a1 = silu_mul(cg[mf][nf][h * 2 + 1], cu[mf][nf][h * 2 + 1]);
                    unsigned hi, lo;
                    split2h(a0, a1, hi, lo);
                    *(unsigned*)(g_shacthi + obase + cc0 + nf * 8) = hi;
                    *(unsigned*)(g_shactlo + obase + cc0 + nf * 8) = lo;
                }
            }
        }
    }
}

// =================== down HMMA (BM=128, BN=128, BK=64) ===================
// expert: 1-term A, stage = A 16K | B 16K = 32K; shared: 2-term A, stage 48K. 3-stage ring.
template<bool SHARED>
__global__ void __launch_bounds__(256, 1) down_hmma(float* __restrict__ Out) {
    constexpr int K_TOT = SHARED ? ISD : ID;
    constexpr int NK = K_TOT / 64;
    constexpr unsigned AH = 0u;
    constexpr unsigned AL = 16384u;                      // shared only
    constexpr unsigned BB0 = SHARED ? 32768u : 16384u;
    constexpr unsigned STG = SHARED ? 49152u : 32768u;
    const int tid = threadIdx.x, l = tid & 31, wid = tid >> 5;
    const int m0 = blockIdx.x * 128, n0 = blockIdx.y * 128;
    const int e = SHARED ? 0 : blockIdx.z;
    int cnt = TT;
    if (!SHARED) { cnt = g_count[e]; if (m0 >= cnt) return; }

    const __half* B = (SHARED ? g_Sd16 : g_Wd16 + (size_t)e * K_TOT * HD) + n0;

    size_t aoff[4];
#pragma unroll
    for (int p = 0; p < 4; p++) {
        int idx = m0 + p * 32 + (tid >> 3);
        if (!SHARED) {
            int ci = idx < cnt ? idx : cnt - 1;
            aoff[p] = (size_t)(g_tok[e][ci] * 2 + g_slot[e][ci]) * K_TOT;
        } else {
            aoff[p] = (size_t)idx * K_TOT;
        }
    }

    extern __shared__ char dyn[];
    unsigned sb = (s2u(dyn) + 127) & ~127u;
    const int kseg = tid & 7;

    auto LOAD = [&](int kt) {
        unsigned bb = sb + (unsigned)(kt % 3) * STG;
        int k0 = kt * 64;
#pragma unroll
        for (int i = 0; i < 4; i++) {
            unsigned d = swz((unsigned)(i * 32 + (tid >> 3)) * 128 + kseg * 16);
            if (SHARED) {
                cpasync16(bb + AH + d, g_shacthi + aoff[i] + k0 + kseg * 8);
                cpasync16(bb + AL + d, g_shactlo + aoff[i] + k0 + kseg * 8);
            } else {
                cpasync16(bb + AH + d, g_act + aoff[i] + k0 + kseg * 8);
            }
        }
#pragma unroll
        for (int i = 0; i < 4; i++) {
            int s = i * 256 + tid;
            int kk = s >> 4, c16 = s & 15;
            unsigned d = (unsigned)(c16 >> 3) * 8192 + swz((unsigned)kk * 128 + (c16 & 7) * 16);
            cpasync16(bb + BB0 + d, B + (size_t)(k0 + kk) * HD + c16 * 8);
        }
        CP_COMMIT();
    };

    float cc[4][4][4] = {};
    const int wm = (wid & 1) * 64, wn = (wid >> 1) * 32;
    const unsigned aRowB = (unsigned)(wm + (l & 15)) * 128;
    const unsigned sx = l & 7;
    const unsigned aCx = (l >> 4) & 1;
    const unsigned bKr = (l & 7) + ((l >> 3) & 1) * 8;
    const unsigned bG2 = (l >> 4) & 1;
    const unsigned hoff = (unsigned)(wn >> 6) * 8192;
    const unsigned nq = ((unsigned)wn & 63) >> 3;
    const unsigned ck0 = ((nq + 0 + bG2) ^ sx) << 4;
    const unsigned ck1 = ((nq + 2 + bG2) ^ sx) << 4;

    auto COMPUTE = [&](int st) {
        unsigned bb = sb + (unsigned)st * STG;
#pragma unroll
        for (int ks = 0; ks < 4; ks++) {
            unsigned cka = (((unsigned)(ks * 2) + aCx) ^ sx) << 4;
            unsigned ah[4][4], al[4][4];
#pragma unroll
            for (int mf = 0; mf < 4; mf++) {
                unsigned ad = bb + aRowB + mf * 2048 + cka;
                ldsm4(ad + AH, ah[mf]);
                if (SHARED) ldsm4(ad + AL, al[mf]);
            }
            unsigned brow = (unsigned)(ks * 16 + bKr) * 128;
            unsigned bh[8];
            ldsm4t(bb + BB0 + hoff + brow + ck0, bh);
            ldsm4t(bb + BB0 + hoff + brow + ck1, bh + 4);
#pragma unroll
            for (int mf = 0; mf < 4; mf++)
#pragma unroll
                for (int nf = 0; nf < 4; nf++) {
                    mma16816(cc[mf][nf], ah[mf], bh + nf * 2);
                    if (SHARED) mma16816(cc[mf][nf], al[mf], bh + nf * 2);
                }
        }
    };

    LOAD(0);
    LOAD(1);
#pragma unroll 1
    for (int kt = 0; kt < NK; kt++) {
        if (kt + 1 < NK) CP_WAIT1(); else CP_WAIT0();
        __syncthreads();
        if (kt + 2 < NK) LOAD(kt + 2);
        COMPUTE(kt % 3);
    }

    const int rr = m0 + wm + (l >> 2);
    const int cc0 = n0 + wn + (l & 3) * 2;
#pragma unroll
    for (int mf = 0; mf < 4; mf++) {
#pragma unroll
        for (int h = 0; h < 2; h++) {
            int r = rr + mf * 16 + h * 8;
            if (!SHARED) {
                if (r >= cnt) continue;
                int flat = g_tok[e][r] * 2 + g_slot[e][r];
                size_t base = (size_t)flat * HD;
#pragma unroll
                for (int nf = 0; nf < 4; nf++) {
                    size_t off = base + cc0 + nf * 8;
                    *(float2*)(g_dslot + off) =
                        make_float2(cc[mf][nf][h * 2 + 0], cc[mf][nf][h * 2 + 1]);
                }
            } else {
                float p0 = g_p[r][0], p1 = g_p[r][1];
                const float* d0 = g_dslot + (size_t)(2 * r) * HD;
                const float* d1 = d0 + HD;
#pragma unroll
                for (int nf = 0; nf < 4; nf++) {
                    int col = cc0 + nf * 8;
                    float2 v0 = *(const float2*)(d0 + col);
                    float2 v1 = *(const float2*)(d1 + col);
                    float2 o;
                    o.x = cc[mf][nf][h * 2 + 0] + p0 * v0.x + p1 * v1.x;
                    o.y = cc[mf][nf][h * 2 + 1] + p0 * v0.y + p1 * v1.y;
                    *(float2*)(Out + (size_t)r * HD + col) = o;
                }
            }
        }
    }
}

// =================== launch ===================
extern "C" void kernel_launch(void* const* d_in, const int* in_sizes, int n_in,
                              void* d_out, int out_size) {
    const float* x      = (const float*)d_in[0];
    const float* gate_w = (const float*)d_in[1];
    const float* Wg     = (const float*)d_in[2];
    const float* Wu     = (const float*)d_in[3];
    const float* Wd     = (const float*)d_in[4];
    const float* Sg     = (const float*)d_in[5];
    const float* Su     = (const float*)d_in[6];
    const float* Sd     = (const float*)d_in[7];
    float* out = (float*)d_out;

    cudaFuncSetAttribute(gateup_hmma<false>, cudaFuncAttributeMaxDynamicSharedMemorySize, 3 * 49152 + 128);
    cudaFuncSetAttribute(gateup_hmma<true>,  cudaFuncAttributeMaxDynamicSharedMemorySize, 3 * 49152 + 128);
    cudaFuncSetAttribute(down_hmma<false>,   cudaFuncAttributeMaxDynamicSharedMemorySize, 3 * 32768 + 128);
    cudaFuncSetAttribute(down_hmma<true>,    cudaFuncAttributeMaxDynamicSharedMemorySize, 3 * 49152 + 128);

    auto conv = [&](const float* src, int sel, size_t n) {
        int n8 = (int)(n / 8);
        conv_kernel<<<(n8 + 255) / 256, 256>>>((const float4*)src, sel, n8);
    };

    zero_counts_kernel<<<1, 32>>>();                                    // 1
    router_kernel<<<TT / 256, 256>>>(x, gate_w);                        // 2
    conv(x,  6, (size_t)TT * HD);                                       // 3
    conv(Wg, 0, (size_t)NE * HD * ID);                                  // 4
    conv(Wu, 1, (size_t)NE * HD * ID);                                  // 5

    dim3 gGU(TT / 128, ID / 128, NE);                                   // 16 x 22 x 8
    gateup_hmma<false><<<gGU, 256, 3 * 49152 + 128>>>();                // 6 <- profile target

    conv(Sg, 3, (size_t)HD * ISD);
    conv(Su, 4, (size_t)HD * ISD);
    dim3 gSGU(TT / 128, ISD / 128);                                     // 16 x 11
    gateup_hmma<true><<<gSGU, 256, 3 * 49152 + 128>>>();

    conv(Wd, 2, (size_t)NE * ID * HD);
    dim3 gD(TT / 128, HD / 128, NE);                                    // 16 x 8 x 8
    down_hmma<false><<<gD, 256, 3 * 32768 + 128>>>(nullptr);

    conv(Sd, 5, (size_t)ISD * HD);
    dim3 gSD(TT / 128, HD / 128);                                       // 16 x 8
    down_hmma<true><<<gSD, 256, 3 * 49152 + 128>>>(out);
}

// round 8
// speedup vs baseline: 4.3872x; 1.0556x over previous
#include <cuda_runtime.h>
#include <cuda_fp16.h>
#include <math.h>

#define TT   2048
#define HD   1024
#define ID   2816
#define NE   8
#define ISD  1408

// ---- routing scratch ----
__device__ int   g_count[NE];
__device__ int   g_tok[NE][TT];
__device__ int   g_slot[NE][TT];
__device__ float g_p[TT][2];
__device__ float g_dslot[(size_t)TT * 2 * HD];

// ---- fp16 operands ----
__device__ __half g_Wg16[(size_t)NE * HD * ID];
__device__ __half g_Wu16[(size_t)NE * HD * ID];
__device__ __half g_Wd16[(size_t)NE * ID * HD];
__device__ __half g_Sg16[(size_t)HD * ISD];
__device__ __half g_Su16[(size_t)HD * ISD];
__device__ __half g_Sd16[(size_t)ISD * HD];
__device__ __half g_x16[(size_t)TT * HD];
__device__ __half g_act[(size_t)TT * 2 * ID];
__device__ __half g_shacthi[(size_t)TT * ISD];
__device__ __half g_shactlo[(size_t)TT * ISD];

// =================== helpers ===================
__device__ __forceinline__ unsigned s2u(const void* p) {
    return (unsigned)__cvta_generic_to_shared(p);
}
__device__ __forceinline__ unsigned swz(unsigned o) { return o ^ ((o >> 3) & 0x70); }

__device__ __forceinline__ void split2h(float f0, float f1, unsigned& hi, unsigned& lo) {
    __half h0 = __float2half_rn(f0);
    __half h1 = __float2half_rn(f1);
    __half l0 = __float2half_rn(f0 - __half2float(h0));
    __half l1 = __float2half_rn(f1 - __half2float(h1));
    hi = (unsigned)__half_as_ushort(h0) | ((unsigned)__half_as_ushort(h1) << 16);
    lo = (unsigned)__half_as_ushort(l0) | ((unsigned)__half_as_ushort(l1) << 16);
}
__device__ __forceinline__ unsigned pack2h(float f0, float f1) {
    __half2 h = __floats2half2_rn(f0, f1);
    return *(unsigned*)&h;
}
__device__ __forceinline__ void cpasync16(unsigned s, const void* g) {
    asm volatile("cp.async.cg.shared.global [%0], [%1], 16;" :: "r"(s), "l"(g));
}
#define CP_COMMIT() asm volatile("cp.async.commit_group;" ::: "memory")
#define CP_WAIT1()  asm volatile("cp.async.wait_group 1;"  ::: "memory")
#define CP_WAIT0()  asm volatile("cp.async.wait_group 0;"  ::: "memory")

__device__ __forceinline__ void ldsm4(unsigned a, unsigned* r) {
    asm volatile("ldmatrix.sync.aligned.m8n8.x4.shared.b16 {%0,%1,%2,%3}, [%4];"
                 : "=r"(r[0]), "=r"(r[1]), "=r"(r[2]), "=r"(r[3]) : "r"(a));
}
__device__ __forceinline__ void ldsm4t(unsigned a, unsigned* r) {
    asm volatile("ldmatrix.sync.aligned.m8n8.x4.trans.shared.b16 {%0,%1,%2,%3}, [%4];"
                 : "=r"(r[0]), "=r"(r[1]), "=r"(r[2]), "=r"(r[3]) : "r"(a));
}
__device__ __forceinline__ void mma16816(float* c, const unsigned* a, const unsigned* b) {
    asm volatile("mma.sync.aligned.m16n8k16.row.col.f32.f16.f16.f32 "
                 "{%0,%1,%2,%3}, {%4,%5,%6,%7}, {%8,%9}, {%0,%1,%2,%3};"
                 : "+f"(c[0]), "+f"(c[1]), "+f"(c[2]), "+f"(c[3])
                 : "r"(a[0]), "r"(a[1]), "r"(a[2]), "r"(a[3]), "r"(b[0]), "r"(b[1]));
}
__device__ __forceinline__ float silu_mul(float g, float u) {
    return u * g / (1.f + __expf(-g));
}

// =================== single conversion kernel (all tensors) ===================
#define NXC (TT * HD / 8)
#define NWC (NE * HD * ID / 8)
#define NSC (HD * ISD / 8)

__global__ void conv_all(const float4* __restrict__ x,  const float4* __restrict__ wg,
                         const float4* __restrict__ wu, const float4* __restrict__ wd,
                         const float4* __restrict__ sg, const float4* __restrict__ su,
                         const float4* __restrict__ sd) {
    long i = (long)blockIdx.x * blockDim.x + threadIdx.x;
    const float4* src; __half* dst;
    if (i < NXC)               { src = x;  dst = g_x16; }
    else if ((i -= NXC) < NWC) { src = wg; dst = g_Wg16; }
    else if ((i -= NWC) < NWC) { src = wu; dst = g_Wu16; }
    else if ((i -= NWC) < NWC) { src = wd; dst = g_Wd16; }
    else if ((i -= NWC) < NSC) { src = sg; dst = g_Sg16; }
    else if ((i -= NSC) < NSC) { src = su; dst = g_Su16; }
    else if ((i -= NSC) < NSC) { src = sd; dst = g_Sd16; }
    else return;
    float4 a = src[2 * i], b = src[2 * i + 1];
    uint4 o;
    o.x = pack2h(a.x, a.y);
    o.y = pack2h(a.z, a.w);
    o.z = pack2h(b.x, b.y);
    o.w = pack2h(b.z, b.w);
    ((uint4*)dst)[i] = o;
}
#define CONV_TOTAL (NXC + 3 * NWC + 3 * NSC)

// =================== router ===================
__global__ void zero_counts_kernel() { if (threadIdx.x < NE) g_count[threadIdx.x] = 0; }

__global__ void router_kernel(const float* __restrict__ x, const float* __restrict__ gw) {
    int t = blockIdx.x * blockDim.x + threadIdx.x;
    if (t >= TT) return;
    float lg[NE];
#pragma unroll
    for (int e = 0; e < NE; e++) lg[e] = 0.f;
    const float* xr = x + (size_t)t * HD;
    for (int h = 0; h < HD; h++) {
        float xv = xr[h];
#pragma unroll
        for (int e = 0; e < NE; e++) lg[e] = fmaf(xv, gw[h * NE + e], lg[e]);
    }
    int i0 = 0; float v0 = lg[0];
#pragma unroll
    for (int e = 1; e < NE; e++) if (lg[e] > v0) { v0 = lg[e]; i0 = e; }
    int i1 = -1; float v1 = -INFINITY;
#pragma unroll
    for (int e = 0; e < NE; e++) if (e != i0 && lg[e] > v1) { v1 = lg[e]; i1 = e; }
    float e1 = expf(v1 - v0);
    float inv = 1.f / (1.f + e1);
    g_p[t][0] = inv;
    g_p[t][1] = e1 * inv;
    int p0 = atomicAdd(&g_count[i0], 1);
    g_tok[i0][p0] = t; g_slot[i0][p0] = 0;
    int p1 = atomicAdd(&g_count[i1], 1);
    g_tok[i1][p1] = t; g_slot[i1][p1] = 1;
}

// =================== gate+up HMMA (merged expert+shared; 512 thr, warp 32x32) ===================
// stage: A 16K | Bg 16K | Bu 16K = 48K; 3-stage ring; z = 0..NE (NE = shared)
#define GU_A  0u
#define GU_BG 16384u
#define GU_BU 32768u
#define GU_STG 49152u

__global__ void __launch_bounds__(512, 1) gateup_hmma() {
    constexpr int NK = HD / 64;
    const int tid = threadIdx.x, l = tid & 31, wid = tid >> 5;
    const int m0 = blockIdx.x * 128, n0 = blockIdx.y * 128;
    const int e = blockIdx.z;
    const bool SH = (e == NE);
    const int N_TOT = SH ? ISD : ID;
    int cnt = TT;
    if (SH) { if (n0 >= ISD) return; }
    else    { cnt = g_count[e]; if (m0 >= cnt) return; }

    const __half* Bg = (SH ? g_Sg16 : g_Wg16 + (size_t)e * HD * ID) + n0;
    const __half* Bu = (SH ? g_Su16 : g_Wu16 + (size_t)e * HD * ID) + n0;

    size_t aoff[2];
#pragma unroll
    for (int p = 0; p < 2; p++) {
        int idx = m0 + p * 64 + (tid >> 3);
        if (!SH) {
            int ci = idx < cnt ? idx : cnt - 1;
            aoff[p] = (size_t)g_tok[e][ci] * HD;
        } else {
            aoff[p] = (size_t)idx * HD;
        }
    }

    extern __shared__ char dyn[];
    unsigned sb = (s2u(dyn) + 127) & ~127u;
    const int kseg = tid & 7;

    auto LOAD = [&](int kt) {
        unsigned bb = sb + (unsigned)(kt % 3) * GU_STG;
        int k0 = kt * 64;
#pragma unroll
        for (int i = 0; i < 2; i++) {
            unsigned d = swz((unsigned)(i * 64 + (tid >> 3)) * 128 + kseg * 16);
            cpasync16(bb + GU_A + d, g_x16 + aoff[i] + k0 + kseg * 8);
        }
#pragma unroll
        for (int i = 0; i < 2; i++) {
            int s = i * 512 + tid;
            int kk = s >> 4, c16 = s & 15;
            unsigned d = (unsigned)(c16 >> 3) * 8192 + swz((unsigned)kk * 128 + (c16 & 7) * 16);
            size_t o = (size_t)(k0 + kk) * N_TOT + c16 * 8;
            cpasync16(bb + GU_BG + d, Bg + o);
            cpasync16(bb + GU_BU + d, Bu + o);
        }
        CP_COMMIT();
    };

    float cg[2][4][4] = {}, cu[2][4][4] = {};
    const int wm = (wid & 3) * 32, wn = (wid >> 2) * 32;
    const unsigned aRowB = (unsigned)(wm + (l & 15)) * 128;
    const unsigned sx = l & 7;
    const unsigned aCx = (l >> 4) & 1;
    const unsigned bKr = (l & 7) + ((l >> 3) & 1) * 8;
    const unsigned bG2 = (l >> 4) & 1;
    const unsigned hoff = (unsigned)(wn >> 6) * 8192;
    const unsigned nq = ((unsigned)wn & 63) >> 3;
    const unsigned ck0 = ((nq + 0 + bG2) ^ sx) << 4;
    const unsigned ck1 = ((nq + 2 + bG2) ^ sx) << 4;

    auto COMPUTE = [&](int st) {
        unsigned bb = sb + (unsigned)st * GU_STG;
#pragma unroll
        for (int ks = 0; ks < 4; ks++) {
            unsigned cka = (((unsigned)(ks * 2) + aCx) ^ sx) << 4;
            unsigned ah[2][4];
#pragma unroll
            for (int mf = 0; mf < 2; mf++)
                ldsm4(bb + GU_A + aRowB + mf * 2048 + cka, ah[mf]);
            unsigned brow = (unsigned)(ks * 16 + bKr) * 128;
            unsigned bg[8], bu[8];
            ldsm4t(bb + GU_BG + hoff + brow + ck0, bg);
            ldsm4t(bb + GU_BG + hoff + brow + ck1, bg + 4);
            ldsm4t(bb + GU_BU + hoff + brow + ck0, bu);
            ldsm4t(bb + GU_BU + hoff + brow + ck1, bu + 4);
#pragma unroll
            for (int mf = 0; mf < 2; mf++)
#pragma unroll
                for (int nf = 0; nf < 4; nf++) {
                    mma16816(cg[mf][nf], ah[mf], bg + nf * 2);
                    mma16816(cu[mf][nf], ah[mf], bu + nf * 2);
                }
        }
    };

    LOAD(0);
    LOAD(1);
#pragma unroll 1
    for (int kt = 0; kt < NK; kt++) {
        if (kt + 1 < NK) CP_WAIT1(); else CP_WAIT0();
        __syncthreads();
        if (kt + 2 < NK) LOAD(kt + 2);
        COMPUTE(kt % 3);
    }

    const int rr = m0 + wm + (l >> 2);
    const int cc0 = n0 + wn + (l & 3) * 2;
#pragma unroll
    for (int mf = 0; mf < 2; mf++) {
#pragma unroll
        for (int h = 0; h < 2; h++) {
            int r = rr + mf * 16 + h * 8;
            if (!SH) {
                if (r >= cnt) continue;
                int flat = g_tok[e][r] * 2 + g_slot[e][r];
                size_t obase = (size_t)flat * ID;
#pragma unroll
                for (int nf = 0; nf < 4; nf++) {
                    float a0 = silu_mul(cg[mf][nf][h * 2 + 0], cu[mf][nf][h * 2 + 0]);
                    float a1 = silu_mul(cg[mf][nf][h * 2 + 1], cu[mf][nf][h * 2 + 1]);
                    *(unsigned*)(g_act + obase + cc0 + nf * 8) = pack2h(a0, a1);
                }
            } else {
                size_t obase = (size_t)r * ISD;
#pragma unroll
                for (int nf = 0; nf < 4; nf++) {
                    float a0 = silu_mul(cg[mf][nf][h * 2 + 0], cu[mf][nf][h * 2 + 0]);
                    float a1 = silu_mul(cg[mf][nf][h * 2 + 1], cu[mf][nf][h * 2 + 1]);
                    unsigned hi, lo;
                    split2h(a0, a1, hi, lo);
                    *(unsigned*)(g_shacthi + obase + cc0 + nf * 8) = hi;
                    *(unsigned*)(g_shactlo + obase + cc0 + nf * 8) = lo;
                }
            }
        }
    }
}

// =================== down HMMA (512 thr, warp 32x32) ===================
// expert: 1-term A, stage A16K|B16K=32K; shared: 2-term A, stage 48K. 3-stage ring.
template<bool SHARED>
__global__ void __launch_bounds__(512, 1) down_hmma(float* __restrict__ Out) {
    constexpr int K_TOT = SHARED ? ISD : ID;
    constexpr int NK = K_TOT / 64;
    constexpr unsigned AH = 0u;
    constexpr unsigned AL = 16384u;
    constexpr unsigned BB0 = SHARED ? 32768u : 16384u;
    constexpr unsigned STG = SHARED ? 49152u : 32768u;
    const int tid = threadIdx.x, l = tid & 31, wid = tid >> 5;
    const int m0 = blockIdx.x * 128, n0 = blockIdx.y * 128;
    const int e = SHARED ? 0 : blockIdx.z;
    int cnt = TT;
    if (!SHARED) { cnt = g_count[e]; if (m0 >= cnt) return; }

    const __half* B = (SHARED ? g_Sd16 : g_Wd16 + (size_t)e * K_TOT * HD) + n0;

    size_t aoff[2];
#pragma unroll
    for (int p = 0; p < 2; p++) {
        int idx = m0 + p * 64 + (tid >> 3);
        if (!SHARED) {
            int ci = idx < cnt ? idx : cnt - 1;
            aoff[p] = (size_t)(g_tok[e][ci] * 2 + g_slot[e][ci]) * K_TOT;
        } else {
            aoff[p] = (size_t)idx * K_TOT;
        }
    }

    extern __shared__ char dyn[];
    unsigned sb = (s2u(dyn) + 127) & ~127u;
    const int kseg = tid & 7;

    auto LOAD = [&](int kt) {
        unsigned bb = sb + (unsigned)(kt % 3) * STG;
        int k0 = kt * 64;
#pragma unroll
        for (int i = 0; i < 2; i++) {
            unsigned d = swz((unsigned)(i * 64 + (tid >> 3)) * 128 + kseg * 16);
            if (SHARED) {
                cpasync16(bb + AH + d, g_shacthi + aoff[i] + k0 + kseg * 8);
                cpasync16(bb + AL + d, g_shactlo + aoff[i] + k0 + kseg * 8);
            } else {
                cpasync16(bb + AH + d, g_act + aoff[i] + k0 + kseg * 8);
            }
        }
#pragma unroll
        for (int i = 0; i < 2; i++) {
            int s = i * 512 + tid;
            int kk = s >> 4, c16 = s & 15;
            unsigned d = (unsigned)(c16 >> 3) * 8192 + swz((unsigned)kk * 128 + (c16 & 7) * 16);
            cpasync16(bb + BB0 + d, B + (size_t)(k0 + kk) * HD + c16 * 8);
        }
        CP_COMMIT();
    };

    float cc[2][4][4] = {};
    const int wm = (wid & 3) * 32, wn = (wid >> 2) * 32;
    const unsigned aRowB = (unsigned)(wm + (l & 15)) * 128;
    const unsigned sx = l & 7;
    const unsigned aCx = (l >> 4) & 1;
    const unsigned bKr = (l & 7) + ((l >> 3) & 1) * 8;
    const unsigned bG2 = (l >> 4) & 1;
    const unsigned hoff = (unsigned)(wn >> 6) * 8192;
    const unsigned nq = ((unsigned)wn & 63) >> 3;
    const unsigned ck0 = ((nq + 0 + bG2) ^ sx) << 4;
    const unsigned ck1 = ((nq + 2 + bG2) ^ sx) << 4;

    auto COMPUTE = [&](int st) {
        unsigned bb = sb + (unsigned)st * STG;
#pragma unroll
        for (int ks = 0; ks < 4; ks++) {
            unsigned cka = (((unsigned)(ks * 2) + aCx) ^ sx) << 4;
            unsigned ah[2][4], al[2][4];
#pragma unroll
            for (int mf = 0; mf < 2; mf++) {
                unsigned ad = bb + aRowB + mf * 2048 + cka;
                ldsm4(ad + AH, ah[mf]);
                if (SHARED) ldsm4(ad + AL, al[mf]);
            }
            unsigned brow = (unsigned)(ks * 16 + bKr) * 128;
            unsigned bh[8];
            ldsm4t(bb + BB0 + hoff + brow + ck0, bh);
            ldsm4t(bb + BB0 + hoff + brow + ck1, bh + 4);
#pragma unroll
            for (int mf = 0; mf < 2; mf++)
#pragma unroll
                for (int nf = 0; nf < 4; nf++) {
                    mma16816(cc[mf][nf], ah[mf], bh + nf * 2);
                    if (SHARED) mma16816(cc[mf][nf], al[mf], bh + nf * 2);
                }
        }
    };

    LOAD(0);
    LOAD(1);
#pragma unroll 1
    for (int kt = 0; kt < NK; kt++) {
        if (kt + 1 < NK) CP_WAIT1(); else CP_WAIT0();
        __syncthreads();
        if (kt + 2 < NK) LOAD(kt + 2);
        COMPUTE(kt % 3);
    }

    const int rr = m0 + wm + (l >> 2);
    const int cc0 = n0 + wn + (l & 3) * 2;
#pragma unroll
    for (int mf = 0; mf < 2; mf++) {
#pragma unroll
        for (int h = 0; h < 2; h++) {
            int r = rr + mf * 16 + h * 8;
            if (!SHARED) {
                if (r >= cnt) continue;
                int flat = g_tok[e][r] * 2 + g_slot[e][r];
                size_t base = (size_t)flat * HD;
#pragma unroll
                for (int nf = 0; nf < 4; nf++) {
                    size_t off = base + cc0 + nf * 8;
                    *(float2*)(g_dslot + off) =
                        make_float2(cc[mf][nf][h * 2 + 0], cc[mf][nf][h * 2 + 1]);
                }
            } else {
                float p0 = g_p[r][0], p1 = g_p[r][1];
                const float* d0 = g_dslot + (size_t)(2 * r) * HD;
                const float* d1 = d0 + HD;
#pragma unroll
                for (int nf = 0; nf < 4; nf++) {
                    int col = cc0 + nf * 8;
                    float2 v0 = *(const float2*)(d0 + col);
                    float2 v1 = *(const float2*)(d1 + col);
                    float2 o;
                    o.x = cc[mf][nf][h * 2 + 0] + p0 * v0.x + p1 * v1.x;
                    o.y = cc[mf][nf][h * 2 + 1] + p0 * v0.y + p1 * v1.y;
                    *(float2*)(Out + (size_t)r * HD + col) = o;
                }
            }
        }
    }
}

// =================== launch ===================
extern "C" void kernel_launch(void* const* d_in, const int* in_sizes, int n_in,
                              void* d_out, int out_size) {
    const float* x      = (const float*)d_in[0];
    const float* gate_w = (const float*)d_in[1];
    const float* Wg     = (const float*)d_in[2];
    const float* Wu     = (const float*)d_in[3];
    const float* Wd     = (const float*)d_in[4];
    const float* Sg     = (const float*)d_in[5];
    const float* Su     = (const float*)d_in[6];
    const float* Sd     = (const float*)d_in[7];
    float* out = (float*)d_out;

    cudaFuncSetAttribute(gateup_hmma,      cudaFuncAttributeMaxDynamicSharedMemorySize, 3 * 49152 + 128);
    cudaFuncSetAttribute(down_hmma<false>, cudaFuncAttributeMaxDynamicSharedMemorySize, 3 * 32768 + 128);
    cudaFuncSetAttribute(down_hmma<true>,  cudaFuncAttributeMaxDynamicSharedMemorySize, 3 * 49152 + 128);

    zero_counts_kernel<<<1, 32>>>();                                    // 1
    router_kernel<<<TT / 256, 256>>>(x, gate_w);                        // 2
    conv_all<<<(CONV_TOTAL + 255) / 256, 256>>>(                        // 3
        (const float4*)x,  (const float4*)Wg, (const float4*)Wu,
        (const float4*)Wd, (const float4*)Sg, (const float4*)Su,
        (const float4*)Sd);

    dim3 gGU(TT / 128, ID / 128, NE + 1);                               // 4: 16 x 22 x 9
    gateup_hmma<<<gGU, 512, 3 * 49152 + 128>>>();

    dim3 gD(TT / 128, HD / 128, NE);                                    // 5: profiled GEMM
    down_hmma<false><<<gD, 512, 3 * 32768 + 128>>>(nullptr);

    dim3 gSD(TT / 128, HD / 128);                                       // 6
    down_hmma<true><<<gSD, 512, 3 * 49152 + 128>>>(out);
}

// round 9
// speedup vs baseline: 4.8145x; 1.0974x over previous
#include <cuda_runtime.h>
#include <cuda_fp16.h>
#include <math.h>

#define TT   2048
#define HD   1024
#define ID   2816
#define NE   8
#define ISD  1408

// ---- routing scratch ----
__device__ int   g_count[NE];
__device__ int   g_tok[NE][TT];
__device__ int   g_slot[NE][TT];
__device__ float g_p[TT][2];
__device__ float g_dslot[(size_t)TT * 2 * HD];

// ---- fp16 operands ----
__device__ __half g_Wg16[(size_t)NE * HD * ID];
__device__ __half g_Wu16[(size_t)NE * HD * ID];
__device__ __half g_Wd16[(size_t)NE * ID * HD];
__device__ __half g_Sg16[(size_t)HD * ISD];
__device__ __half g_Su16[(size_t)HD * ISD];
__device__ __half g_Sd16[(size_t)ISD * HD];
__device__ __half g_x16[(size_t)TT * HD];
__device__ __half g_act[(size_t)TT * 2 * ID];
__device__ __half g_shact[(size_t)TT * ISD];

// =================== helpers ===================
__device__ __forceinline__ unsigned s2u(const void* p) {
    return (unsigned)__cvta_generic_to_shared(p);
}
__device__ __forceinline__ unsigned swz(unsigned o) { return o ^ ((o >> 3) & 0x70); }

__device__ __forceinline__ unsigned pack2h(float f0, float f1) {
    __half2 h = __floats2half2_rn(f0, f1);
    return *(unsigned*)&h;
}
__device__ __forceinline__ void cpasync16(unsigned s, const void* g) {
    asm volatile("cp.async.cg.shared.global [%0], [%1], 16;" :: "r"(s), "l"(g));
}
#define CP_COMMIT() asm volatile("cp.async.commit_group;" ::: "memory")
#define CP_WAIT1()  asm volatile("cp.async.wait_group 1;"  ::: "memory")
#define CP_WAIT0()  asm volatile("cp.async.wait_group 0;"  ::: "memory")

__device__ __forceinline__ void ldsm4(unsigned a, unsigned* r) {
    asm volatile("ldmatrix.sync.aligned.m8n8.x4.shared.b16 {%0,%1,%2,%3}, [%4];"
                 : "=r"(r[0]), "=r"(r[1]), "=r"(r[2]), "=r"(r[3]) : "r"(a));
}
__device__ __forceinline__ void ldsm4t(unsigned a, unsigned* r) {
    asm volatile("ldmatrix.sync.aligned.m8n8.x4.trans.shared.b16 {%0,%1,%2,%3}, [%4];"
                 : "=r"(r[0]), "=r"(r[1]), "=r"(r[2]), "=r"(r[3]) : "r"(a));
}
__device__ __forceinline__ void mma16816(float* c, const unsigned* a, const unsigned* b) {
    asm volatile("mma.sync.aligned.m16n8k16.row.col.f32.f16.f16.f32 "
                 "{%0,%1,%2,%3}, {%4,%5,%6,%7}, {%8,%9}, {%0,%1,%2,%3};"
                 : "+f"(c[0]), "+f"(c[1]), "+f"(c[2]), "+f"(c[3])
                 : "r"(a[0]), "r"(a[1]), "r"(a[2]), "r"(a[3]), "r"(b[0]), "r"(b[1]));
}
__device__ __forceinline__ float silu_mul(float g, float u) {
    return u * g / (1.f + __expf(-g));
}

// =================== single conversion kernel ===================
#define NXC (TT * HD / 8)
#define NWC (NE * HD * ID / 8)
#define NSC (HD * ISD / 8)

__global__ void conv_all(const float4* __restrict__ x,  const float4* __restrict__ wg,
                         const float4* __restrict__ wu, const float4* __restrict__ wd,
                         const float4* __restrict__ sg, const float4* __restrict__ su,
                         const float4* __restrict__ sd) {
    long i = (long)blockIdx.x * blockDim.x + threadIdx.x;
    const float4* src; __half* dst;
    if (i < NXC)               { src = x;  dst = g_x16; }
    else if ((i -= NXC) < NWC) { src = wg; dst = g_Wg16; }
    else if ((i -= NWC) < NWC) { src = wu; dst = g_Wu16; }
    else if ((i -= NWC) < NWC) { src = wd; dst = g_Wd16; }
    else if ((i -= NWC) < NSC) { src = sg; dst = g_Sg16; }
    else if ((i -= NSC) < NSC) { src = su; dst = g_Su16; }
    else if ((i -= NSC) < NSC) { src = sd; dst = g_Sd16; }
    else return;
    float4 a = src[2 * i], b = src[2 * i + 1];
    uint4 o;
    o.x = pack2h(a.x, a.y);
    o.y = pack2h(a.z, a.w);
    o.z = pack2h(b.x, b.y);
    o.w = pack2h(b.z, b.w);
    ((uint4*)dst)[i] = o;
}
#define CONV_TOTAL (NXC + 3 * NWC + 3 * NSC)

// =================== router ===================
__global__ void zero_counts_kernel() { if (threadIdx.x < NE) g_count[threadIdx.x] = 0; }

__global__ void router_kernel(const float* __restrict__ x, const float* __restrict__ gw) {
    int t = blockIdx.x * blockDim.x + threadIdx.x;
    if (t >= TT) return;
    float lg[NE];
#pragma unroll
    for (int e = 0; e < NE; e++) lg[e] = 0.f;
    const float* xr = x + (size_t)t * HD;
    for (int h = 0; h < HD; h++) {
        float xv = xr[h];
#pragma unroll
        for (int e = 0; e < NE; e++) lg[e] = fmaf(xv, gw[h * NE + e], lg[e]);
    }
    int i0 = 0; float v0 = lg[0];
#pragma unroll
    for (int e = 1; e < NE; e++) if (lg[e] > v0) { v0 = lg[e]; i0 = e; }
    int i1 = -1; float v1 = -INFINITY;
#pragma unroll
    for (int e = 0; e < NE; e++) if (e != i0 && lg[e] > v1) { v1 = lg[e]; i1 = e; }
    float e1 = expf(v1 - v0);
    float inv = 1.f / (1.f + e1);
    g_p[t][0] = inv;
    g_p[t][1] = e1 * inv;
    int p0 = atomicAdd(&g_count[i0], 1);
    g_tok[i0][p0] = t; g_slot[i0][p0] = 0;
    int p1 = atomicAdd(&g_count[i1], 1);
    g_tok[i1][p1] = t; g_slot[i1][p1] = 1;
}

// =================== gate+up HMMA (256 thr, BM=128, BN=64, 2 CTAs/SM) ===================
// stage: A 16K | Bg 8K | Bu 8K = 32K; 3-stage ring; z = 0..NE (NE = shared)
#define GU_A  0u
#define GU_BG 16384u
#define GU_BU 24576u
#define GU_STG 32768u

__global__ void __launch_bounds__(256, 2) gateup_hmma() {
    constexpr int NK = HD / 64;
    const int tid = threadIdx.x, l = tid & 31, wid = tid >> 5;
    const int m0 = blockIdx.x * 128, n0 = blockIdx.y * 64;
    const int e = blockIdx.z;
    const bool SH = (e == NE);
    const int N_TOT = SH ? ISD : ID;
    int cnt = TT;
    if (SH) { if (n0 >= ISD) return; }
    else    { cnt = g_count[e]; if (m0 >= cnt) return; }

    const __half* Bg = (SH ? g_Sg16 : g_Wg16 + (size_t)e * HD * ID) + n0;
    const __half* Bu = (SH ? g_Su16 : g_Wu16 + (size_t)e * HD * ID) + n0;

    size_t aoff[4];
#pragma unroll
    for (int p = 0; p < 4; p++) {
        int idx = m0 + p * 32 + (tid >> 3);
        if (!SH) {
            int ci = idx < cnt ? idx : cnt - 1;
            aoff[p] = (size_t)g_tok[e][ci] * HD;
        } else {
            aoff[p] = (size_t)idx * HD;
        }
    }

    extern __shared__ char dyn[];
    unsigned sb = (s2u(dyn) + 127) & ~127u;
    const int kseg = tid & 7;

    auto LOAD = [&](int kt) {
        unsigned bb = sb + (unsigned)(kt % 3) * GU_STG;
        int k0 = kt * 64;
#pragma unroll
        for (int i = 0; i < 4; i++) {
            unsigned d = swz((unsigned)(i * 32 + (tid >> 3)) * 128 + kseg * 16);
            cpasync16(bb + GU_A + d, g_x16 + aoff[i] + k0 + kseg * 8);
        }
#pragma unroll
        for (int i = 0; i < 2; i++) {
            int s = i * 256 + tid;
            int kk = s >> 3, c8 = s & 7;
            unsigned d = swz((unsigned)kk * 128 + c8 * 16);
            size_t o = (size_t)(k0 + kk) * N_TOT + c8 * 8;
            cpasync16(bb + GU_BG + d, Bg + o);
            cpasync16(bb + GU_BU + d, Bu + o);
        }
        CP_COMMIT();
    };

    float cg[2][4][4] = {}, cu[2][4][4] = {};
    const int wm = (wid & 3) * 32, wn = (wid >> 2) * 32;
    const unsigned aRowB = (unsigned)(wm + (l & 15)) * 128;
    const unsigned sx = l & 7;
    const unsigned aCx = (l >> 4) & 1;
    const unsigned bKr = (l & 7) + ((l >> 3) & 1) * 8;
    const unsigned bG2 = (l >> 4) & 1;
    const unsigned nq = (unsigned)wn >> 3;
    const unsigned ck0 = ((nq + 0 + bG2) ^ sx) << 4;
    const unsigned ck1 = ((nq + 2 + bG2) ^ sx) << 4;

    auto COMPUTE = [&](int st) {
        unsigned bb = sb + (unsigned)st * GU_STG;
#pragma unroll
        for (int ks = 0; ks < 4; ks++) {
            unsigned cka = (((unsigned)(ks * 2) + aCx) ^ sx) << 4;
            unsigned ah[2][4];
#pragma unroll
            for (int mf = 0; mf < 2; mf++)
                ldsm4(bb + GU_A + aRowB + mf * 2048 + cka, ah[mf]);
            unsigned brow = (unsigned)(ks * 16 + bKr) * 128;
            unsigned bg[8], bu[8];
            ldsm4t(bb + GU_BG + brow + ck0, bg);
            ldsm4t(bb + GU_BG + brow + ck1, bg + 4);
            ldsm4t(bb + GU_BU + brow + ck0, bu);
            ldsm4t(bb + GU_BU + brow + ck1, bu + 4);
#pragma unroll
            for (int mf = 0; mf < 2; mf++)
#pragma unroll
                for (int nf = 0; nf < 4; nf++) {
                    mma16816(cg[mf][nf], ah[mf], bg + nf * 2);
                    mma16816(cu[mf][nf], ah[mf], bu + nf * 2);
                }
        }
    };

    LOAD(0);
    LOAD(1);
#pragma unroll 1
    for (int kt = 0; kt < NK; kt++) {
        if (kt + 1 < NK) CP_WAIT1(); else CP_WAIT0();
        __syncthreads();
        if (kt + 2 < NK) LOAD(kt + 2);
        COMPUTE(kt % 3);
    }

    const int rr = m0 + wm + (l >> 2);
    const int cc0 = n0 + wn + (l & 3) * 2;
    __half* O = SH ? g_shact : g_act;
#pragma unroll
    for (int mf = 0; mf < 2; mf++) {
#pragma unroll
        for (int h = 0; h < 2; h++) {
            int r = rr + mf * 16 + h * 8;
            size_t obase;
            if (!SH) {
                if (r >= cnt) continue;
                int flat = g_tok[e][r] * 2 + g_slot[e][r];
                obase = (size_t)flat * ID;
            } else {
                obase = (size_t)r * ISD;
            }
#pragma unroll
            for (int nf = 0; nf < 4; nf++) {
                float a0 = silu_mul(cg[mf][nf][h * 2 + 0], cu[mf][nf][h * 2 + 0]);
                float a1 = silu_mul(cg[mf][nf][h * 2 + 1], cu[mf][nf][h * 2 + 1]);
                *(unsigned*)(O + obase + cc0 + nf * 8) = pack2h(a0, a1);
            }
        }
    }
}

// =================== down HMMA (256 thr, BM=128, BN=64, 2 CTAs/SM) ===================
// stage: A 16K | B 8K = 24K; 3-stage ring
#define DN_A 0u
#define DN_B 16384u
#define DN_STG 24576u

template<bool SHARED>
__global__ void __launch_bounds__(256, 2) down_hmma(float* __restrict__ Out) {
    constexpr int K_TOT = SHARED ? ISD : ID;
    constexpr int NK = K_TOT / 64;
    const int tid = threadIdx.x, l = tid & 31, wid = tid >> 5;
    const int m0 = blockIdx.x * 128, n0 = blockIdx.y * 64;
    const int e = SHARED ? 0 : blockIdx.z;
    int cnt = TT;
    if (!SHARED) { cnt = g_count[e]; if (m0 >= cnt) return; }

    const __half* B = (SHARED ? g_Sd16 : g_Wd16 + (size_t)e * K_TOT * HD) + n0;
    const __half* A = SHARED ? g_shact : g_act;

    size_t aoff[4];
#pragma unroll
    for (int p = 0; p < 4; p++) {
        int idx = m0 + p * 32 + (tid >> 3);
        if (!SHARED) {
            int ci = idx < cnt ? idx : cnt - 1;
            aoff[p] = (size_t)(g_tok[e][ci] * 2 + g_slot[e][ci]) * K_TOT;
        } else {
            aoff[p] = (size_t)idx * K_TOT;
        }
    }

    extern __shared__ char dyn[];
    unsigned sb = (s2u(dyn) + 127) & ~127u;
    const int kseg = tid & 7;

    auto LOAD = [&](int kt) {
        unsigned bb = sb + (unsigned)(kt % 3) * DN_STG;
        int k0 = kt * 64;
#pragma unroll
        for (int i = 0; i < 4; i++) {
            unsigned d = swz((unsigned)(i * 32 + (tid >> 3)) * 128 + kseg * 16);
            cpasync16(bb + DN_A + d, A + aoff[i] + k0 + kseg * 8);
        }
#pragma unroll
        for (int i = 0; i < 2; i++) {
            int s = i * 256 + tid;
            int kk = s >> 3, c8 = s & 7;
            unsigned d = swz((unsigned)kk * 128 + c8 * 16);
            cpasync16(bb + DN_B + d, B + (size_t)(k0 + kk) * HD + c8 * 8);
        }
        CP_COMMIT();
    };

    float cc[2][4][4] = {};
    const int wm = (wid & 3) * 32, wn = (wid >> 2) * 32;
    const unsigned aRowB = (unsigned)(wm + (l & 15)) * 128;
    const unsigned sx = l & 7;
    const unsigned aCx = (l >> 4) & 1;
    const unsigned bKr = (l & 7) + ((l >> 3) & 1) * 8;
    const unsigned bG2 = (l >> 4) & 1;
    const unsigned nq = (unsigned)wn >> 3;
    const unsigned ck0 = ((nq + 0 + bG2) ^ sx) << 4;
    const unsigned ck1 = ((nq + 2 + bG2) ^ sx) << 4;

    auto COMPUTE = [&](int st) {
        unsigned bb = sb + (unsigned)st * DN_STG;
#pragma unroll
        for (int ks = 0; ks < 4; ks++) {
            unsigned cka = (((unsigned)(ks * 2) + aCx) ^ sx) << 4;
            unsigned ah[2][4];
#pragma unroll
            for (int mf = 0; mf < 2; mf++)
                ldsm4(bb + DN_A + aRowB + mf * 2048 + cka, ah[mf]);
            unsigned brow = (unsigned)(ks * 16 + bKr) * 128;
            unsigned bh[8];
            ldsm4t(bb + DN_B + brow + ck0, bh);
            ldsm4t(bb + DN_B + brow + ck1, bh + 4);
#pragma unroll
            for (int mf = 0; mf < 2; mf++)
#pragma unroll
                for (int nf = 0; nf < 4; nf++)
                    mma16816(cc[mf][nf], ah[mf], bh + nf * 2);
        }
    };

    LOAD(0);
    LOAD(1);
#pragma unroll 1
    for (int kt = 0; kt < NK; kt++) {
        if (kt + 1 < NK) CP_WAIT1(); else CP_WAIT0();
        __syncthreads();
        if (kt + 2 < NK) LOAD(kt + 2);
        COMPUTE(kt % 3);
    }

    const int rr = m0 + wm + (l >> 2);
    const int cc0 = n0 + wn + (l & 3) * 2;
#pragma unroll
    for (int mf = 0; mf < 2; mf++) {
#pragma unroll
        for (int h = 0; h < 2; h++) {
            int r = rr + mf * 16 + h * 8;
            if (!SHARED) {
                if (r >= cnt) continue;
                int flat = g_tok[e][r] * 2 + g_slot[e][r];
                size_t base = (size_t)flat * HD;
#pragma unroll
                for (int nf = 0; nf < 4; nf++) {
                    size_t off = base + cc0 + nf * 8;
                    *(float2*)(g_dslot + off) =
                        make_float2(cc[mf][nf][h * 2 + 0], cc[mf][nf][h * 2 + 1]);
                }
            } else {
                float p0 = g_p[r][0], p1 = g_p[r][1];
                const float* d0 = g_dslot + (size_t)(2 * r) * HD;
                const float* d1 = d0 + HD;
#pragma unroll
                for (int nf = 0; nf < 4; nf++) {
                    int col = cc0 + nf * 8;
                    float2 v0 = *(const float2*)(d0 + col);
                    float2 v1 = *(const float2*)(d1 + col);
                    float2 o;
                    o.x = cc[mf][nf][h * 2 + 0] + p0 * v0.x + p1 * v1.x;
                    o.y = cc[mf][nf][h * 2 + 1] + p0 * v0.y + p1 * v1.y;
                    *(float2*)(Out + (size_t)r * HD + col) = o;
                }
            }
        }
    }
}

// =================== launch ===================
extern "C" void kernel_launch(void* const* d_in, const int* in_sizes, int n_in,
                              void* d_out, int out_size) {
    const float* x      = (const float*)d_in[0];
    const float* gate_w = (const float*)d_in[1];
    const float* Wg     = (const float*)d_in[2];
    const float* Wu     = (const float*)d_in[3];
    const float* Wd     = (const float*)d_in[4];
    const float* Sg     = (const float*)d_in[5];
    const float* Su     = (const float*)d_in[6];
    const float* Sd     = (const float*)d_in[7];
    float* out = (float*)d_out;

    cudaFuncSetAttribute(gateup_hmma,      cudaFuncAttributeMaxDynamicSharedMemorySize, 3 * 32768 + 128);
    cudaFuncSetAttribute(down_hmma<false>, cudaFuncAttributeMaxDynamicSharedMemorySize, 3 * 24576 + 128);
    cudaFuncSetAttribute(down_hmma<true>,  cudaFuncAttributeMaxDynamicSharedMemorySize, 3 * 24576 + 128);

    zero_counts_kernel<<<1, 32>>>();                                    // 1
    router_kernel<<<TT / 256, 256>>>(x, gate_w);                        // 2
    conv_all<<<(CONV_TOTAL + 255) / 256, 256>>>(                        // 3
        (const float4*)x,  (const float4*)Wg, (const float4*)Wu,
        (const float4*)Wd, (const float4*)Sg, (const float4*)Su,
        (const float4*)Sd);

    dim3 gGU(TT / 128, ID / 64, NE + 1);                                // 4: 16 x 44 x 9
    gateup_hmma<<<gGU, 256, 3 * 32768 + 128>>>();

    dim3 gD(TT / 128, HD / 64, NE);                                     // 5: 16 x 16 x 8
    down_hmma<false><<<gD, 256, 3 * 24576 + 128>>>(nullptr);

    dim3 gSD(TT / 128, HD / 64);                                        // 6: 16 x 16
    down_hmma<true><<<gSD, 256, 3 * 24576 + 128>>>(out);
}

// round 10
// speedup vs baseline: 4.9803x; 1.0344x over previous
#include <cuda_runtime.h>
#include <cuda_fp16.h>
#include <math.h>

#define TT   2048
#define HD   1024
#define ID   2816
#define NE   8
#define ISD  1408

// ---- routing scratch ----
__device__ int   g_count[NE];
__device__ int   g_tok[NE][TT];
__device__ int   g_slot[NE][TT];
__device__ float g_p[TT][2];
__device__ float g_dslot[(size_t)TT * 2 * HD];

// ---- fp16 operands ----
__device__ __half g_Wg16[(size_t)NE * HD * ID];
__device__ __half g_Wu16[(size_t)NE * HD * ID];
__device__ __half g_Wd16[(size_t)NE * ID * HD];
__device__ __half g_Sg16[(size_t)HD * ISD];
__device__ __half g_Su16[(size_t)HD * ISD];
__device__ __half g_Sd16[(size_t)ISD * HD];
__device__ __half g_x16[(size_t)TT * HD];
__device__ __half g_act[(size_t)TT * 2 * ID];
__device__ __half g_shact[(size_t)TT * ISD];

// =================== helpers ===================
__device__ __forceinline__ unsigned s2u(const void* p) {
    return (unsigned)__cvta_generic_to_shared(p);
}
__device__ __forceinline__ unsigned swz(unsigned o) { return o ^ ((o >> 3) & 0x70); }

__device__ __forceinline__ unsigned pack2h(float f0, float f1) {
    __half2 h = __floats2half2_rn(f0, f1);
    return *(unsigned*)&h;
}
__device__ __forceinline__ void cpasync16(unsigned s, const void* g) {
    asm volatile("cp.async.cg.shared.global [%0], [%1], 16;" :: "r"(s), "l"(g));
}
#define CP_COMMIT() asm volatile("cp.async.commit_group;" ::: "memory")
#define CP_WAIT1()  asm volatile("cp.async.wait_group 1;"  ::: "memory")
#define CP_WAIT0()  asm volatile("cp.async.wait_group 0;"  ::: "memory")

__device__ __forceinline__ void ldsm4(unsigned a, unsigned* r) {
    asm volatile("ldmatrix.sync.aligned.m8n8.x4.shared.b16 {%0,%1,%2,%3}, [%4];"
                 : "=r"(r[0]), "=r"(r[1]), "=r"(r[2]), "=r"(r[3]) : "r"(a));
}
__device__ __forceinline__ void ldsm4t(unsigned a, unsigned* r) {
    asm volatile("ldmatrix.sync.aligned.m8n8.x4.trans.shared.b16 {%0,%1,%2,%3}, [%4];"
                 : "=r"(r[0]), "=r"(r[1]), "=r"(r[2]), "=r"(r[3]) : "r"(a));
}
__device__ __forceinline__ void mma16816(float* c, const unsigned* a, const unsigned* b) {
    asm volatile("mma.sync.aligned.m16n8k16.row.col.f32.f16.f16.f32 "
                 "{%0,%1,%2,%3}, {%4,%5,%6,%7}, {%8,%9}, {%0,%1,%2,%3};"
                 : "+f"(c[0]), "+f"(c[1]), "+f"(c[2]), "+f"(c[3])
                 : "r"(a[0]), "r"(a[1]), "r"(a[2]), "r"(a[3]), "r"(b[0]), "r"(b[1]));
}
__device__ __forceinline__ float silu_mul(float g, float u) {
    return u * g / (1.f + __expf(-g));
}

// =================== single conversion kernel ===================
#define NXC (TT * HD / 8)
#define NWC (NE * HD * ID / 8)
#define NSC (HD * ISD / 8)

__global__ void conv_all(const float4* __restrict__ x,  const float4* __restrict__ wg,
                         const float4* __restrict__ wu, const float4* __restrict__ wd,
                         const float4* __restrict__ sg, const float4* __restrict__ su,
                         const float4* __restrict__ sd) {
    long i = (long)blockIdx.x * blockDim.x + threadIdx.x;
    const float4* src; __half* dst;
    if (i < NXC)               { src = x;  dst = g_x16; }
    else if ((i -= NXC) < NWC) { src = wg; dst = g_Wg16; }
    else if ((i -= NWC) < NWC) { src = wu; dst = g_Wu16; }
    else if ((i -= NWC) < NWC) { src = wd; dst = g_Wd16; }
    else if ((i -= NWC) < NSC) { src = sg; dst = g_Sg16; }
    else if ((i -= NSC) < NSC) { src = su; dst = g_Su16; }
    else if ((i -= NSC) < NSC) { src = sd; dst = g_Sd16; }
    else return;
    float4 a = src[2 * i], b = src[2 * i + 1];
    uint4 o;
    o.x = pack2h(a.x, a.y);
    o.y = pack2h(a.z, a.w);
    o.z = pack2h(b.x, b.y);
    o.w = pack2h(b.z, b.w);
    ((uint4*)dst)[i] = o;
}
#define CONV_TOTAL (NXC + 3 * NWC + 3 * NSC)

// =================== router ===================
__global__ void zero_counts_kernel() { if (threadIdx.x < NE) g_count[threadIdx.x] = 0; }

__global__ void router_kernel(const float* __restrict__ x, const float* __restrict__ gw) {
    int t = blockIdx.x * blockDim.x + threadIdx.x;
    if (t >= TT) return;
    float lg[NE];
#pragma unroll
    for (int e = 0; e < NE; e++) lg[e] = 0.f;
    const float* xr = x + (size_t)t * HD;
    for (int h = 0; h < HD; h++) {
        float xv = xr[h];
#pragma unroll
        for (int e = 0; e < NE; e++) lg[e] = fmaf(xv, gw[h * NE + e], lg[e]);
    }
    int i0 = 0; float v0 = lg[0];
#pragma unroll
    for (int e = 1; e < NE; e++) if (lg[e] > v0) { v0 = lg[e]; i0 = e; }
    int i1 = -1; float v1 = -INFINITY;
#pragma unroll
    for (int e = 0; e < NE; e++) if (e != i0 && lg[e] > v1) { v1 = lg[e]; i1 = e; }
    float e1 = expf(v1 - v0);
    float inv = 1.f / (1.f + e1);
    g_p[t][0] = inv;
    g_p[t][1] = e1 * inv;
    int p0 = atomicAdd(&g_count[i0], 1);
    g_tok[i0][p0] = t; g_slot[i0][p0] = 0;
    int p1 = atomicAdd(&g_count[i1], 1);
    g_tok[i1][p1] = t; g_slot[i1][p1] = 1;
}

// =================== gate+up HMMA (256 thr, BM=128, BN=64, 2 CTAs/SM) ===================
// stage: A 16K | Bg 8K | Bu 8K = 32K; 3-stage ring; z = 0..NE (NE = shared)
#define GU_A  0u
#define GU_BG 16384u
#define GU_BU 24576u
#define GU_STG 32768u

__global__ void __launch_bounds__(256, 2) gateup_hmma() {
    constexpr int NK = HD / 64;
    const int tid = threadIdx.x, l = tid & 31, wid = tid >> 5;
    const int m0 = blockIdx.x * 128, n0 = blockIdx.y * 64;
    const int e = blockIdx.z;
    const bool SH = (e == NE);
    const int N_TOT = SH ? ISD : ID;
    int cnt = TT;
    if (SH) { if (n0 >= ISD) return; }
    else    { cnt = g_count[e]; if (m0 >= cnt) return; }

    const __half* Bg = (SH ? g_Sg16 : g_Wg16 + (size_t)e * HD * ID) + n0;
    const __half* Bu = (SH ? g_Su16 : g_Wu16 + (size_t)e * HD * ID) + n0;

    size_t aoff[4];
#pragma unroll
    for (int p = 0; p < 4; p++) {
        int idx = m0 + p * 32 + (tid >> 3);
        if (!SH) {
            int ci = idx < cnt ? idx : cnt - 1;
            aoff[p] = (size_t)g_tok[e][ci] * HD;
        } else {
            aoff[p] = (size_t)idx * HD;
        }
    }

    extern __shared__ char dyn[];
    unsigned sb = (s2u(dyn) + 127) & ~127u;
    const int kseg = tid & 7;

    auto LOAD = [&](int kt) {
        unsigned bb = sb + (unsigned)(kt % 3) * GU_STG;
        int k0 = kt * 64;
#pragma unroll
        for (int i = 0; i < 4; i++) {
            unsigned d = swz((unsigned)(i * 32 + (tid >> 3)) * 128 + kseg * 16);
            cpasync16(bb + GU_A + d, g_x16 + aoff[i] + k0 + kseg * 8);
        }
#pragma unroll
        for (int i = 0; i < 2; i++) {
            int s = i * 256 + tid;
            int kk = s >> 3, c8 = s & 7;
            unsigned d = swz((unsigned)kk * 128 + c8 * 16);
            size_t o = (size_t)(k0 + kk) * N_TOT + c8 * 8;
            cpasync16(bb + GU_BG + d, Bg + o);
            cpasync16(bb + GU_BU + d, Bu + o);
        }
        CP_COMMIT();
    };

    float cg[2][4][4] = {}, cu[2][4][4] = {};
    const int wm = (wid & 3) * 32, wn = (wid >> 2) * 32;
    const unsigned aRowB = (unsigned)(wm + (l & 15)) * 128;
    const unsigned sx = l & 7;
    const unsigned aCx = (l >> 4) & 1;
    const unsigned bKr = (l & 7) + ((l >> 3) & 1) * 8;
    const unsigned bG2 = (l >> 4) & 1;
    const unsigned nq = (unsigned)wn >> 3;
    const unsigned ck0 = ((nq + 0 + bG2) ^ sx) << 4;
    const unsigned ck1 = ((nq + 2 + bG2) ^ sx) << 4;

    auto COMPUTE = [&](int st) {
        unsigned bb = sb + (unsigned)st * GU_STG;
#pragma unroll
        for (int ks = 0; ks < 4; ks++) {
            unsigned cka = (((unsigned)(ks * 2) + aCx) ^ sx) << 4;
            unsigned ah[2][4];
#pragma unroll
            for (int mf = 0; mf < 2; mf++)
                ldsm4(bb + GU_A + aRowB + mf * 2048 + cka, ah[mf]);
            unsigned brow = (unsigned)(ks * 16 + bKr) * 128;
            unsigned bg[8], bu[8];
            ldsm4t(bb + GU_BG + brow + ck0, bg);
            ldsm4t(bb + GU_BG + brow + ck1, bg + 4);
            ldsm4t(bb + GU_BU + brow + ck0, bu);
            ldsm4t(bb + GU_BU + brow + ck1, bu + 4);
#pragma unroll
            for (int mf = 0; mf < 2; mf++)
#pragma unroll
                for (int nf = 0; nf < 4; nf++) {
                    mma16816(cg[mf][nf], ah[mf], bg + nf * 2);
                    mma16816(cu[mf][nf], ah[mf], bu + nf * 2);
                }
        }
    };

    LOAD(0);
    LOAD(1);
#pragma unroll 1
    for (int kt = 0; kt < NK; kt++) {
        if (kt + 1 < NK) CP_WAIT1(); else CP_WAIT0();
        __syncthreads();
        if (kt + 2 < NK) LOAD(kt + 2);
        COMPUTE(kt % 3);
    }

    const int rr = m0 + wm + (l >> 2);
    const int cc0 = n0 + wn + (l & 3) * 2;
    __half* O = SH ? g_shact : g_act;
#pragma unroll
    for (int mf = 0; mf < 2; mf++) {
#pragma unroll
        for (int h = 0; h < 2; h++) {
            int r = rr + mf * 16 + h * 8;
            size_t obase;
            if (!SH) {
                if (r >= cnt) continue;
                int flat = g_tok[e][r] * 2 + g_slot[e][r];
                obase = (size_t)flat * ID;
            } else {
                obase = (size_t)r * ISD;
            }
#pragma unroll
            for (int nf = 0; nf < 4; nf++) {
                float a0 = silu_mul(cg[mf][nf][h * 2 + 0], cu[mf][nf][h * 2 + 0]);
                float a1 = silu_mul(cg[mf][nf][h * 2 + 1], cu[mf][nf][h * 2 + 1]);
                *(unsigned*)(O + obase + cc0 + nf * 8) = pack2h(a0, a1);
            }
        }
    }
}

// =================== down HMMA (256 thr, BM=128, BN=128, warp 32x64, 2 CTAs/SM) ===================
// stage: A 16K | B 16K (two 8K n-halves) = 32K; 3-stage ring
#define DN_A 0u
#define DN_B 16384u
#define DN_STG 32768u

template<bool SHARED>
__global__ void __launch_bounds__(256, 2) down_hmma(float* __restrict__ Out) {
    constexpr int K_TOT = SHARED ? ISD : ID;
    constexpr int NK = K_TOT / 64;
    const int tid = threadIdx.x, l = tid & 31, wid = tid >> 5;
    const int m0 = blockIdx.x * 128, n0 = blockIdx.y * 128;
    const int e = SHARED ? 0 : blockIdx.z;
    int cnt = TT;
    if (!SHARED) { cnt = g_count[e]; if (m0 >= cnt) return; }

    const __half* B = (SHARED ? g_Sd16 : g_Wd16 + (size_t)e * K_TOT * HD) + n0;
    const __half* A = SHARED ? g_shact : g_act;

    size_t aoff[4];
#pragma unroll
    for (int p = 0; p < 4; p++) {
        int idx = m0 + p * 32 + (tid >> 3);
        if (!SHARED) {
            int ci = idx < cnt ? idx : cnt - 1;
            aoff[p] = (size_t)(g_tok[e][ci] * 2 + g_slot[e][ci]) * K_TOT;
        } else {
            aoff[p] = (size_t)idx * K_TOT;
        }
    }

    extern __shared__ char dyn[];
    unsigned sb = (s2u(dyn) + 127) & ~127u;
    const int kseg = tid & 7;

    auto LOAD = [&](int kt) {
        unsigned bb = sb + (unsigned)(kt % 3) * DN_STG;
        int k0 = kt * 64;
#pragma unroll
        for (int i = 0; i < 4; i++) {
            unsigned d = swz((unsigned)(i * 32 + (tid >> 3)) * 128 + kseg * 16);
            cpasync16(bb + DN_A + d, A + aoff[i] + k0 + kseg * 8);
        }
#pragma unroll
        for (int i = 0; i < 4; i++) {
            int s = i * 256 + tid;
            int kk = s >> 4, c16 = s & 15;
            unsigned d = (unsigned)(c16 >> 3) * 8192 + swz((unsigned)kk * 128 + (c16 & 7) * 16);
            cpasync16(bb + DN_B + d, B + (size_t)(k0 + kk) * HD + c16 * 8);
        }
        CP_COMMIT();
    };

    float cc[2][8][4] = {};
    const int wm = (wid & 3) * 32, wn = (wid >> 2) * 64;
    const unsigned aRowB = (unsigned)(wm + (l & 15)) * 128;
    const unsigned sx = l & 7;
    const unsigned aCx = (l >> 4) & 1;
    const unsigned bKr = (l & 7) + ((l >> 3) & 1) * 8;
    const unsigned bG2 = (l >> 4) & 1;
    const unsigned hoff = (unsigned)(wn >> 6) * 8192;   // n-half select
    unsigned ck[4];
#pragma unroll
    for (int j = 0; j < 4; j++) ck[j] = (((unsigned)(2 * j) + bG2) ^ sx) << 4;

    auto COMPUTE = [&](int st) {
        unsigned bb = sb + (unsigned)st * DN_STG;
#pragma unroll
        for (int ks = 0; ks < 4; ks++) {
            unsigned cka = (((unsigned)(ks * 2) + aCx) ^ sx) << 4;
            unsigned ah[2][4];
#pragma unroll
            for (int mf = 0; mf < 2; mf++)
                ldsm4(bb + DN_A + aRowB + mf * 2048 + cka, ah[mf]);
            unsigned brow = (unsigned)(ks * 16 + bKr) * 128;
            unsigned bh[16];
#pragma unroll
            for (int j = 0; j < 4; j++)
                ldsm4t(bb + DN_B + hoff + brow + ck[j], bh + 4 * j);
#pragma unroll
            for (int mf = 0; mf < 2; mf++)
#pragma unroll
                for (int nf = 0; nf < 8; nf++)
                    mma16816(cc[mf][nf], ah[mf], bh + nf * 2);
        }
    };

    LOAD(0);
    LOAD(1);
#pragma unroll 1
    for (int kt = 0; kt < NK; kt++) {
        if (kt + 1 < NK) CP_WAIT1(); else CP_WAIT0();
        __syncthreads();
        if (kt + 2 < NK) LOAD(kt + 2);
        COMPUTE(kt % 3);
    }

    const int rr = m0 + wm + (l >> 2);
    const int cc0 = n0 + wn + (l & 3) * 2;
#pragma unroll
    for (int mf = 0; mf < 2; mf++) {
#pragma unroll
        for (int h = 0; h < 2; h++) {
            int r = rr + mf * 16 + h * 8;
            if (!SHARED) {
                if (r >= cnt) continue;
                int flat = g_tok[e][r] * 2 + g_slot[e][r];
                size_t base = (size_t)flat * HD;
#pragma unroll
                for (int nf = 0; nf < 8; nf++) {
                    size_t off = base + cc0 + nf * 8;
                    *(float2*)(g_dslot + off) =
                        make_float2(cc[mf][nf][h * 2 + 0], cc[mf][nf][h * 2 + 1]);
                }
            } else {
                float p0 = g_p[r][0], p1 = g_p[r][1];
                const float* d0 = g_dslot + (size_t)(2 * r) * HD;
                const float* d1 = d0 + HD;
#pragma unroll
                for (int nf = 0; nf < 8; nf++) {
                    int col = cc0 + nf * 8;
                    float2 v0 = *(const float2*)(d0 + col);
                    float2 v1 = *(const float2*)(d1 + col);
                    float2 o;
                    o.x = cc[mf][nf][h * 2 + 0] + p0 * v0.x + p1 * v1.x;
                    o.y = cc[mf][nf][h * 2 + 1] + p0 * v0.y + p1 * v1.y;
                    *(float2*)(Out + (size_t)r * HD + col) = o;
                }
            }
        }
    }
}

// =================== launch ===================
extern "C" void kernel_launch(void* const* d_in, const int* in_sizes, int n_in,
                              void* d_out, int out_size) {
    const float* x      = (const float*)d_in[0];
    const float* gate_w = (const float*)d_in[1];
    const float* Wg     = (const float*)d_in[2];
    const float* Wu     = (const float*)d_in[3];
    const float* Wd     = (const float*)d_in[4];
    const float* Sg     = (const float*)d_in[5];
    const float* Su     = (const float*)d_in[6];
    const float* Sd     = (const float*)d_in[7];
    float* out = (float*)d_out;

    cudaFuncSetAttribute(gateup_hmma,      cudaFuncAttributeMaxDynamicSharedMemorySize, 3 * 32768 + 128);
    cudaFuncSetAttribute(down_hmma<false>, cudaFuncAttributeMaxDynamicSharedMemorySize, 3 * 32768 + 128);
    cudaFuncSetAttribute(down_hmma<true>,  cudaFuncAttributeMaxDynamicSharedMemorySize, 3 * 32768 + 128);

    zero_counts_kernel<<<1, 32>>>();                                    // 1
    router_kernel<<<TT / 256, 256>>>(x, gate_w);                        // 2
    conv_all<<<(CONV_TOTAL + 255) / 256, 256>>>(                        // 3
        (const float4*)x,  (const float4*)Wg, (const float4*)Wu,
        (const float4*)Wd, (const float4*)Sg, (const float4*)Su,
        (const float4*)Sd);

    dim3 gGU(TT / 128, ID / 64, NE + 1);                                // 4: 16 x 44 x 9
    gateup_hmma<<<gGU, 256, 3 * 32768 + 128>>>();

    dim3 gD(TT / 128, HD / 128, NE);                                    // 5: 16 x 8 x 8
    down_hmma<false><<<gD, 256, 3 * 32768 + 128>>>(nullptr);

    dim3 gSD(TT / 128, HD / 128);                                       // 6: 16 x 8
    down_hmma<true><<<gSD, 256, 3 * 32768 + 128>>>(out);
}

// round 11
// speedup vs baseline: 5.0062x; 1.0052x over previous
#include <cuda_runtime.h>
#include <cuda_fp16.h>
#include <math.h>

#define TT   2048
#define HD   1024
#define ID   2816
#define NE   8
#define ISD  1408

// ---- routing scratch ----
__device__ int   g_count[NE];
__device__ int   g_tok[NE][TT];
__device__ int   g_slot[NE][TT];
__device__ float g_p[TT][2];

// ---- split-K partial buffers (fp32, non-atomic, deterministic) ----
__device__ float g_dp0[(size_t)TT * 2 * HD];
__device__ float g_dp1[(size_t)TT * 2 * HD];
__device__ float g_shp0[(size_t)TT * HD];
__device__ float g_shp1[(size_t)TT * HD];

// ---- fp16 operands ----
__device__ __half g_Wg16[(size_t)NE * HD * ID];
__device__ __half g_Wu16[(size_t)NE * HD * ID];
__device__ __half g_Wd16[(size_t)NE * ID * HD];
__device__ __half g_Sg16[(size_t)HD * ISD];
__device__ __half g_Su16[(size_t)HD * ISD];
__device__ __half g_Sd16[(size_t)ISD * HD];
__device__ __half g_x16[(size_t)TT * HD];
__device__ __half g_act[(size_t)TT * 2 * ID];
__device__ __half g_shact[(size_t)TT * ISD];

// =================== helpers ===================
__device__ __forceinline__ unsigned s2u(const void* p) {
    return (unsigned)__cvta_generic_to_shared(p);
}
__device__ __forceinline__ unsigned swz(unsigned o) { return o ^ ((o >> 3) & 0x70); }

__device__ __forceinline__ unsigned pack2h(float f0, float f1) {
    __half2 h = __floats2half2_rn(f0, f1);
    return *(unsigned*)&h;
}
__device__ __forceinline__ void cpasync16(unsigned s, const void* g) {
    asm volatile("cp.async.cg.shared.global [%0], [%1], 16;" :: "r"(s), "l"(g));
}
#define CP_COMMIT() asm volatile("cp.async.commit_group;" ::: "memory")
#define CP_WAIT1()  asm volatile("cp.async.wait_group 1;"  ::: "memory")
#define CP_WAIT0()  asm volatile("cp.async.wait_group 0;"  ::: "memory")

__device__ __forceinline__ void ldsm4(unsigned a, unsigned* r) {
    asm volatile("ldmatrix.sync.aligned.m8n8.x4.shared.b16 {%0,%1,%2,%3}, [%4];"
                 : "=r"(r[0]), "=r"(r[1]), "=r"(r[2]), "=r"(r[3]) : "r"(a));
}
__device__ __forceinline__ void ldsm4t(unsigned a, unsigned* r) {
    asm volatile("ldmatrix.sync.aligned.m8n8.x4.trans.shared.b16 {%0,%1,%2,%3}, [%4];"
                 : "=r"(r[0]), "=r"(r[1]), "=r"(r[2]), "=r"(r[3]) : "r"(a));
}
__device__ __forceinline__ void mma16816(float* c, const unsigned* a, const unsigned* b) {
    asm volatile("mma.sync.aligned.m16n8k16.row.col.f32.f16.f16.f32 "
                 "{%0,%1,%2,%3}, {%4,%5,%6,%7}, {%8,%9}, {%0,%1,%2,%3};"
                 : "+f"(c[0]), "+f"(c[1]), "+f"(c[2]), "+f"(c[3])
                 : "r"(a[0]), "r"(a[1]), "r"(a[2]), "r"(a[3]), "r"(b[0]), "r"(b[1]));
}
__device__ __forceinline__ float silu_mul(float g, float u) {
    return u * g / (1.f + __expf(-g));
}

// =================== single conversion kernel ===================
#define NXC (TT * HD / 8)
#define NWC (NE * HD * ID / 8)
#define NSC (HD * ISD / 8)

__global__ void conv_all(const float4* __restrict__ x,  const float4* __restrict__ wg,
                         const float4* __restrict__ wu, const float4* __restrict__ wd,
                         const float4* __restrict__ sg, const float4* __restrict__ su,
                         const float4* __restrict__ sd) {
    long i = (long)blockIdx.x * blockDim.x + threadIdx.x;
    const float4* src; __half* dst;
    if (i < NXC)               { src = x;  dst = g_x16; }
    else if ((i -= NXC) < NWC) { src = wg; dst = g_Wg16; }
    else if ((i -= NWC) < NWC) { src = wu; dst = g_Wu16; }
    else if ((i -= NWC) < NWC) { src = wd; dst = g_Wd16; }
    else if ((i -= NWC) < NSC) { src = sg; dst = g_Sg16; }
    else if ((i -= NSC) < NSC) { src = su; dst = g_Su16; }
    else if ((i -= NSC) < NSC) { src = sd; dst = g_Sd16; }
    else return;
    float4 a = src[2 * i], b = src[2 * i + 1];
    uint4 o;
    o.x = pack2h(a.x, a.y);
    o.y = pack2h(a.z, a.w);
    o.z = pack2h(b.x, b.y);
    o.w = pack2h(b.z, b.w);
    ((uint4*)dst)[i] = o;
}
#define CONV_TOTAL (NXC + 3 * NWC + 3 * NSC)

// =================== router ===================
__global__ void zero_counts_kernel() { if (threadIdx.x < NE) g_count[threadIdx.x] = 0; }

__global__ void router_kernel(const float* __restrict__ x, const float* __restrict__ gw) {
    int t = blockIdx.x * blockDim.x + threadIdx.x;
    if (t >= TT) return;
    float lg[NE];
#pragma unroll
    for (int e = 0; e < NE; e++) lg[e] = 0.f;
    const float* xr = x + (size_t)t * HD;
    for (int h = 0; h < HD; h++) {
        float xv = xr[h];
#pragma unroll
        for (int e = 0; e < NE; e++) lg[e] = fmaf(xv, gw[h * NE + e], lg[e]);
    }
    int i0 = 0; float v0 = lg[0];
#pragma unroll
    for (int e = 1; e < NE; e++) if (lg[e] > v0) { v0 = lg[e]; i0 = e; }
    int i1 = -1; float v1 = -INFINITY;
#pragma unroll
    for (int e = 0; e < NE; e++) if (e != i0 && lg[e] > v1) { v1 = lg[e]; i1 = e; }
    float e1 = expf(v1 - v0);
    float inv = 1.f / (1.f + e1);
    g_p[t][0] = inv;
    g_p[t][1] = e1 * inv;
    int p0 = atomicAdd(&g_count[i0], 1);
    g_tok[i0][p0] = t; g_slot[i0][p0] = 0;
    int p1 = atomicAdd(&g_count[i1], 1);
    g_tok[i1][p1] = t; g_slot[i1][p1] = 1;
}

// =================== gate+up HMMA (256 thr, BM=128, BN=64, 2 CTAs/SM) ===================
// stage: A 16K | Bg 8K | Bu 8K = 32K; 3-stage ring; z = 0..NE (NE = shared)
#define GU_A  0u
#define GU_BG 16384u
#define GU_BU 24576u
#define GU_STG 32768u

__global__ void __launch_bounds__(256, 2) gateup_hmma() {
    constexpr int NK = HD / 64;
    const int tid = threadIdx.x, l = tid & 31, wid = tid >> 5;
    const int m0 = blockIdx.x * 128, n0 = blockIdx.y * 64;
    const int e = blockIdx.z;
    const bool SH = (e == NE);
    const int N_TOT = SH ? ISD : ID;
    int cnt = TT;
    if (SH) { if (n0 >= ISD) return; }
    else    { cnt = g_count[e]; if (m0 >= cnt) return; }

    const __half* Bg = (SH ? g_Sg16 : g_Wg16 + (size_t)e * HD * ID) + n0;
    const __half* Bu = (SH ? g_Su16 : g_Wu16 + (size_t)e * HD * ID) + n0;

    size_t aoff[4];
#pragma unroll
    for (int p = 0; p < 4; p++) {
        int idx = m0 + p * 32 + (tid >> 3);
        if (!SH) {
            int ci = idx < cnt ? idx : cnt - 1;
            aoff[p] = (size_t)g_tok[e][ci] * HD;
        } else {
            aoff[p] = (size_t)idx * HD;
        }
    }

    extern __shared__ char dyn[];
    unsigned sb = (s2u(dyn) + 127) & ~127u;
    const int kseg = tid & 7;

    auto LOAD = [&](int kt) {
        unsigned bb = sb + (unsigned)(kt % 3) * GU_STG;
        int k0 = kt * 64;
#pragma unroll
        for (int i = 0; i < 4; i++) {
            unsigned d = swz((unsigned)(i * 32 + (tid >> 3)) * 128 + kseg * 16);
            cpasync16(bb + GU_A + d, g_x16 + aoff[i] + k0 + kseg * 8);
        }
#pragma unroll
        for (int i = 0; i < 2; i++) {
            int s = i * 256 + tid;
            int kk = s >> 3, c8 = s & 7;
            unsigned d = swz((unsigned)kk * 128 + c8 * 16);
            size_t o = (size_t)(k0 + kk) * N_TOT + c8 * 8;
            cpasync16(bb + GU_BG + d, Bg + o);
            cpasync16(bb + GU_BU + d, Bu + o);
        }
        CP_COMMIT();
    };

    float cg[2][4][4] = {}, cu[2][4][4] = {};
    const int wm = (wid & 3) * 32, wn = (wid >> 2) * 32;
    const unsigned aRowB = (unsigned)(wm + (l & 15)) * 128;
    const unsigned sx = l & 7;
    const unsigned aCx = (l >> 4) & 1;
    const unsigned bKr = (l & 7) + ((l >> 3) & 1) * 8;
    const unsigned bG2 = (l >> 4) & 1;
    const unsigned nq = (unsigned)wn >> 3;
    const unsigned ck0 = ((nq + 0 + bG2) ^ sx) << 4;
    const unsigned ck1 = ((nq + 2 + bG2) ^ sx) << 4;

    auto COMPUTE = [&](int st) {
        unsigned bb = sb + (unsigned)st * GU_STG;
#pragma unroll
        for (int ks = 0; ks < 4; ks++) {
            unsigned cka = (((unsigned)(ks * 2) + aCx) ^ sx) << 4;
            unsigned ah[2][4];
#pragma unroll
            for (int mf = 0; mf < 2; mf++)
                ldsm4(bb + GU_A + aRowB + mf * 2048 + cka, ah[mf]);
            unsigned brow = (unsigned)(ks * 16 + bKr) * 128;
            unsigned bg[8], bu[8];
            ldsm4t(bb + GU_BG + brow + ck0, bg);
            ldsm4t(bb + GU_BG + brow + ck1, bg + 4);
            ldsm4t(bb + GU_BU + brow + ck0, bu);
            ldsm4t(bb + GU_BU + brow + ck1, bu + 4);
#pragma unroll
            for (int mf = 0; mf < 2; mf++)
#pragma unroll
                for (int nf = 0; nf < 4; nf++) {
                    mma16816(cg[mf][nf], ah[mf], bg + nf * 2);
                    mma16816(cu[mf][nf], ah[mf], bu + nf * 2);
                }
        }
    };

    LOAD(0);
    LOAD(1);
#pragma unroll 1
    for (int kt = 0; kt < NK; kt++) {
        if (kt + 1 < NK) CP_WAIT1(); else CP_WAIT0();
        __syncthreads();
        if (kt + 2 < NK) LOAD(kt + 2);
        COMPUTE(kt % 3);
    }

    const int rr = m0 + wm + (l >> 2);
    const int cc0 = n0 + wn + (l & 3) * 2;
    __half* O = SH ? g_shact : g_act;
#pragma unroll
    for (int mf = 0; mf < 2; mf++) {
#pragma unroll
        for (int h = 0; h < 2; h++) {
            int r = rr + mf * 16 + h * 8;
            size_t obase;
            if (!SH) {
                if (r >= cnt) continue;
                int flat = g_tok[e][r] * 2 + g_slot[e][r];
                obase = (size_t)flat * ID;
            } else {
                obase = (size_t)r * ISD;
            }
#pragma unroll
            for (int nf = 0; nf < 4; nf++) {
                float a0 = silu_mul(cg[mf][nf][h * 2 + 0], cu[mf][nf][h * 2 + 0]);
                float a1 = silu_mul(cg[mf][nf][h * 2 + 1], cu[mf][nf][h * 2 + 1]);
                *(unsigned*)(O + obase + cc0 + nf * 8) = pack2h(a0, a1);
            }
        }
    }
}

// =================== merged down HMMA (split-K x2, expert + shared in one launch) ===================
// z = 0..15: expert e = z>>1, split s = z&1   (K 2816 -> halves of 1408 = 22 k-tiles)
// z = 16..17: shared, split s = z-16          (K 1408 -> halves of  704 = 11 k-tiles)
// BM=128, BN=128, warp 32x64; stage A16K|B16K=32K, 3-stage ring, 2 CTAs/SM
#define DN_A 0u
#define DN_B 16384u
#define DN_STG 32768u

__global__ void __launch_bounds__(256, 2) down_hmma() {
    const int tid = threadIdx.x, l = tid & 31, wid = tid >> 5;
    const int m0 = blockIdx.x * 128, n0 = blockIdx.y * 128;
    const int z = blockIdx.z;
    const bool SH = (z >= 2 * NE);
    const int s  = SH ? (z - 2 * NE) : (z & 1);
    const int e  = SH ? 0 : (z >> 1);
    const int nkt = SH ? (ISD / 128) : (ID / 128);       // 11 or 22 k-tiles of 64
    const int kb  = s * (SH ? (ISD / 2) : (ID / 2));     // split base
    const int astr = SH ? ISD : ID;
    int cnt = TT;
    if (!SH) { cnt = g_count[e]; if (m0 >= cnt) return; }

    const __half* B = (SH ? g_Sd16 : g_Wd16 + (size_t)e * ID * HD) + (size_t)kb * HD + n0;
    const __half* A = SH ? g_shact : g_act;

    size_t aoff[4];
#pragma unroll
    for (int p = 0; p < 4; p++) {
        int idx = m0 + p * 32 + (tid >> 3);
        if (!SH) {
            int ci = idx < cnt ? idx : cnt - 1;
            aoff[p] = (size_t)(g_tok[e][ci] * 2 + g_slot[e][ci]) * astr + kb;
        } else {
            aoff[p] = (size_t)idx * astr + kb;
        }
    }

    extern __shared__ char dyn[];
    unsigned sb = (s2u(dyn) + 127) & ~127u;
    const int kseg = tid & 7;

    auto LOAD = [&](int kt) {
        unsigned bb = sb + (unsigned)(kt % 3) * DN_STG;
        int k0 = kt * 64;
#pragma unroll
        for (int i = 0; i < 4; i++) {
            unsigned d = swz((unsigned)(i * 32 + (tid >> 3)) * 128 + kseg * 16);
            cpasync16(bb + DN_A + d, A + aoff[i] + k0 + kseg * 8);
        }
#pragma unroll
        for (int i = 0; i < 4; i++) {
            int sidx = i * 256 + tid;
            int kk = sidx >> 4, c16 = sidx & 15;
            unsigned d = (unsigned)(c16 >> 3) * 8192 + swz((unsigned)kk * 128 + (c16 & 7) * 16);
            cpasync16(bb + DN_B + d, B + (size_t)(k0 + kk) * HD + c16 * 8);
        }
        CP_COMMIT();
    };

    float cc[2][8][4] = {};
    const int wm = (wid & 3) * 32, wn = (wid >> 2) * 64;
    const unsigned aRowB = (unsigned)(wm + (l & 15)) * 128;
    const unsigned sx = l & 7;
    const unsigned aCx = (l >> 4) & 1;
    const unsigned bKr = (l & 7) + ((l >> 3) & 1) * 8;
    const unsigned bG2 = (l >> 4) & 1;
    const unsigned hoff = (unsigned)(wn >> 6) * 8192;   // n-half select
    unsigned ck[4];
#pragma unroll
    for (int j = 0; j < 4; j++) ck[j] = (((unsigned)(2 * j) + bG2) ^ sx) << 4;

    auto COMPUTE = [&](int st) {
        unsigned bb = sb + (unsigned)st * DN_STG;
#pragma unroll
        for (int ks = 0; ks < 4; ks++) {
            unsigned cka = (((unsigned)(ks * 2) + aCx) ^ sx) << 4;
            unsigned ah[2][4];
#pragma unroll
            for (int mf = 0; mf < 2; mf++)
                ldsm4(bb + DN_A + aRowB + mf * 2048 + cka, ah[mf]);
            unsigned brow = (unsigned)(ks * 16 + bKr) * 128;
            unsigned bh[16];
#pragma unroll
            for (int j = 0; j < 4; j++)
                ldsm4t(bb + DN_B + hoff + brow + ck[j], bh + 4 * j);
#pragma unroll
            for (int mf = 0; mf < 2; mf++)
#pragma unroll
                for (int nf = 0; nf < 8; nf++)
                    mma16816(cc[mf][nf], ah[mf], bh + nf * 2);
        }
    };

    LOAD(0);
    LOAD(1);
#pragma unroll 1
    for (int kt = 0; kt < nkt; kt++) {
        if (kt + 1 < nkt) CP_WAIT1(); else CP_WAIT0();
        __syncthreads();
        if (kt + 2 < nkt) LOAD(kt + 2);
        COMPUTE(kt % 3);
    }

    const int rr = m0 + wm + (l >> 2);
    const int cc0 = n0 + wn + (l & 3) * 2;
    float* OutP = SH ? (s ? g_shp1 : g_shp0) : (s ? g_dp1 : g_dp0);
#pragma unroll
    for (int mf = 0; mf < 2; mf++) {
#pragma unroll
        for (int h = 0; h < 2; h++) {
            int r = rr + mf * 16 + h * 8;
            if (!SH) {
                if (r >= cnt) continue;
                int tok = g_tok[e][r], slot = g_slot[e][r];
                float pw = g_p[tok][slot];
                size_t base = (size_t)(tok * 2 + slot) * HD;
#pragma unroll
                for (int nf = 0; nf < 8; nf++) {
                    size_t off = base + cc0 + nf * 8;
                    *(float2*)(OutP + off) =
                        make_float2(pw * cc[mf][nf][h * 2 + 0], pw * cc[mf][nf][h * 2 + 1]);
                }
            } else {
                size_t base = (size_t)r * HD;
#pragma unroll
                for (int nf = 0; nf < 8; nf++) {
                    size_t off = base + cc0 + nf * 8;
                    *(float2*)(OutP + off) =
                        make_float2(cc[mf][nf][h * 2 + 0], cc[mf][nf][h * 2 + 1]);
                }
            }
        }
    }
}

// =================== final combine: out = shp0+shp1 + dp0[t,0]+dp0[t,1]+dp1[t,0]+dp1[t,1] ===================
__global__ void combine_kernel(float4* __restrict__ out) {
    int i = blockIdx.x * blockDim.x + threadIdx.x;
    if (i >= TT * HD / 4) return;
    int t  = i / (HD / 4);
    int c4 = i & (HD / 4 - 1);
    size_t b0 = (size_t)(2 * t) * (HD / 4) + c4;
    size_t b1 = b0 + (HD / 4);
    float4 s0 = ((const float4*)g_shp0)[i];
    float4 s1 = ((const float4*)g_shp1)[i];
    float4 a0 = ((const float4*)g_dp0)[b0];
    float4 a1 = ((const float4*)g_dp0)[b1];
    float4 a2 = ((const float4*)g_dp1)[b0];
    float4 a3 = ((const float4*)g_dp1)[b1];
    float4 o;
    o.x = s0.x + s1.x + a0.x + a1.x + a2.x + a3.x;
    o.y = s0.y + s1.y + a0.y + a1.y + a2.y + a3.y;
    o.z = s0.z + s1.z + a0.z + a1.z + a2.z + a3.z;
    o.w = s0.w + s1.w + a0.w + a1.w + a2.w + a3.w;
    out[i] = o;
}

// =================== launch ===================
extern "C" void kernel_launch(void* const* d_in, const int* in_sizes, int n_in,
                              void* d_out, int out_size) {
    const float* x      = (const float*)d_in[0];
    const float* gate_w = (const float*)d_in[1];
    const float* Wg     = (const float*)d_in[2];
    const float* Wu     = (const float*)d_in[3];
    const float* Wd     = (const float*)d_in[4];
    const float* Sg     = (const float*)d_in[5];
    const float* Su     = (const float*)d_in[6];
    const float* Sd     = (const float*)d_in[7];
    float* out = (float*)d_out;

    cudaFuncSetAttribute(gateup_hmma, cudaFuncAttributeMaxDynamicSharedMemorySize, 3 * 32768 + 128);
    cudaFuncSetAttribute(down_hmma,   cudaFuncAttributeMaxDynamicSharedMemorySize, 3 * 32768 + 128);

    zero_counts_kernel<<<1, 32>>>();                                    // 1
    router_kernel<<<TT / 256, 256>>>(x, gate_w);                        // 2
    conv_all<<<(CONV_TOTAL + 255) / 256, 256>>>(                        // 3
        (const float4*)x,  (const float4*)Wg, (const float4*)Wu,
        (const float4*)Wd, (const float4*)Sg, (const float4*)Su,
        (const float4*)Sd);

    dim3 gGU(TT / 128, ID / 64, NE + 1);                                // 4: 16 x 44 x 9
    gateup_hmma<<<gGU, 256, 3 * 32768 + 128>>>();

    dim3 gD(TT / 128, HD / 128, 2 * NE + 2);                            // 5: 16 x 8 x 18
    down_hmma<<<gD, 256, 3 * 32768 + 128>>>();

    combine_kernel<<<(TT * HD / 4 + 255) / 256, 256>>>((float4*)out);   // 6
}